// round 3
// baseline (speedup 1.0000x reference)
#include <cuda_runtime.h>
#include <math.h>

#define BATCH 256
#define GHH 100
#define GWW 100
#define CH 32
#define TPAST 20
#define TFUT 30

// Ping-pong scratch for the conv stack (sanctioned __device__ global scratch).
__device__ __align__(128) float g_bufA[(size_t)BATCH*GHH*GWW*CH];
__device__ __align__(128) float g_bufB[(size_t)BATCH*GHH*GWW*CH];

// ---------------------------------------------------------------------------
// conv0: 2ch -> 32ch, 2x2 kernel, pad (0,1)x(0,1), relu. One thread per pixel.
// ---------------------------------------------------------------------------
__global__ void conv0_kernel(const float* __restrict__ lidar,
                             const float* __restrict__ w,
                             const float* __restrict__ bias) {
    __shared__ __align__(16) float sw[256];
    __shared__ float sb[32];
    int tid = threadIdx.x;
    if (tid < 256) sw[tid] = w[tid];
    if (tid < 32)  sb[tid] = bias[tid];
    __syncthreads();
    int p = blockIdx.x * blockDim.x + tid;
    if (p >= BATCH * GHH * GWW) return;
    int b   = p / (GHH * GWW);
    int rem = p % (GHH * GWW);
    int y = rem / GWW, x = rem % GWW;

    float a[8];
#pragma unroll
    for (int dy = 0; dy < 2; dy++)
#pragma unroll
        for (int dx = 0; dx < 2; dx++) {
            int yy = y + dy, xx = x + dx;
            bool ok = (yy < GHH) && (xx < GWW);
            const float* ip = lidar + ((size_t)(b * GHH + yy) * GWW + xx) * 2;
            a[(dy * 2 + dx) * 2 + 0] = ok ? ip[0] : 0.f;
            a[(dy * 2 + dx) * 2 + 1] = ok ? ip[1] : 0.f;
        }

    float acc[32];
#pragma unroll
    for (int c = 0; c < 32; c++) acc[c] = sb[c];
#pragma unroll
    for (int k = 0; k < 8; k++) {
        float av = a[k];
        const float4* w4 = reinterpret_cast<const float4*>(&sw[k * 32]);
#pragma unroll
        for (int q = 0; q < 8; q++) {
            float4 wv = w4[q];
            acc[4 * q + 0] += av * wv.x;
            acc[4 * q + 1] += av * wv.y;
            acc[4 * q + 2] += av * wv.z;
            acc[4 * q + 3] += av * wv.w;
        }
    }
    float4* op = reinterpret_cast<float4*>(&g_bufA[(size_t)p * 32]);
#pragma unroll
    for (int q = 0; q < 8; q++) {
        float4 v;
        v.x = fmaxf(acc[4 * q + 0], 0.f);
        v.y = fmaxf(acc[4 * q + 1], 0.f);
        v.z = fmaxf(acc[4 * q + 2], 0.f);
        v.w = fmaxf(acc[4 * q + 3], 0.f);
        op[q] = v;
    }
}

// ---------------------------------------------------------------------------
// convN: 32ch -> 32ch, 2x2 kernel, pad (0,1)x(0,1), relu.
// 16x16 pixel tile per block, 128 threads, 2 pixels x 32 channels per thread.
// smem input tile pitch 33 floats -> conflict-free activation loads.
// ---------------------------------------------------------------------------
#define TILE 16
#define SPITCH 33
#define SMEM_IN_BYTES (17 * 17 * SPITCH * 4)

__global__ void convN_kernel(const float* __restrict__ w,
                             const float* __restrict__ bias,
                             int srcIsA) {
    extern __shared__ float s_in[];                 // [17*17][33]
    __shared__ __align__(16) float s_w[4096];       // [4][32][32]
    __shared__ float s_b[32];

    const float* in   = srcIsA ? g_bufA : g_bufB;
    float*       outp = srcIsA ? g_bufB : g_bufA;

    int tid = threadIdx.x;                          // 128
    int b   = blockIdx.z;
    int by  = blockIdx.y * TILE, bx = blockIdx.x * TILE;

    for (int i = tid; i < 1024; i += 128)
        reinterpret_cast<float4*>(s_w)[i] = reinterpret_cast<const float4*>(w)[i];
    if (tid < 32) s_b[tid] = bias[tid];

    // Load 17x17x32 input tile (zero-padded past the grid edge).
    for (int i = tid; i < 289 * 8; i += 128) {
        int pix = i >> 3, j = i & 7;
        int r = pix / 17, c = pix % 17;
        int gy = by + r, gx = bx + c;
        float4 v = make_float4(0.f, 0.f, 0.f, 0.f);
        if (gy < GHH && gx < GWW)
            v = reinterpret_cast<const float4*>(
                    in + ((size_t)(b * GHH + gy) * GWW + gx) * 32)[j];
        float* dp = s_in + pix * SPITCH + j * 4;
        dp[0] = v.x; dp[1] = v.y; dp[2] = v.z; dp[3] = v.w;
    }
    __syncthreads();

    int tx = tid & 15, ty0 = tid >> 4;              // ty0 in 0..7
    float acc0[32], acc1[32];
#pragma unroll
    for (int c = 0; c < 32; c++) { acc0[c] = s_b[c]; acc1[c] = s_b[c]; }

#pragma unroll
    for (int dy = 0; dy < 2; dy++)
#pragma unroll
        for (int dx = 0; dx < 2; dx++) {
            const float* i0 = s_in + ((ty0 + dy) * 17 + tx + dx) * SPITCH;
            const float* i1 = s_in + ((ty0 + 8 + dy) * 17 + tx + dx) * SPITCH;
            const float* wp = s_w + (dy * 2 + dx) * 1024;
#pragma unroll 4
            for (int ci = 0; ci < 32; ci++) {
                float a0 = i0[ci], a1 = i1[ci];
                const float4* w4 = reinterpret_cast<const float4*>(wp + ci * 32);
#pragma unroll
                for (int q = 0; q < 8; q++) {
                    float4 wv = w4[q];
                    acc0[4 * q + 0] += a0 * wv.x; acc0[4 * q + 1] += a0 * wv.y;
                    acc0[4 * q + 2] += a0 * wv.z; acc0[4 * q + 3] += a0 * wv.w;
                    acc1[4 * q + 0] += a1 * wv.x; acc1[4 * q + 1] += a1 * wv.y;
                    acc1[4 * q + 2] += a1 * wv.z; acc1[4 * q + 3] += a1 * wv.w;
                }
            }
        }

    int gx = bx + tx;
    if (gx < GWW) {
        int gy0 = by + ty0;
        if (gy0 < GHH) {
            float4* op = reinterpret_cast<float4*>(
                outp + ((size_t)(b * GHH + gy0) * GWW + gx) * 32);
#pragma unroll
            for (int q = 0; q < 8; q++)
                op[q] = make_float4(fmaxf(acc0[4 * q + 0], 0.f), fmaxf(acc0[4 * q + 1], 0.f),
                                    fmaxf(acc0[4 * q + 2], 0.f), fmaxf(acc0[4 * q + 3], 0.f));
        }
        int gy1 = by + ty0 + 8;
        if (gy1 < GHH) {
            float4* op = reinterpret_cast<float4*>(
                outp + ((size_t)(b * GHH + gy1) * GWW + gx) * 32);
#pragma unroll
            for (int q = 0; q < 8; q++)
                op[q] = make_float4(fmaxf(acc1[4 * q + 0], 0.f), fmaxf(acc1[4 * q + 1], 0.f),
                                    fmaxf(acc1[4 * q + 2], 0.f), fmaxf(acc1[4 * q + 3], 0.f));
        }
    }
}

// ---------------------------------------------------------------------------
// Fused GRU encoder + autoregressive decoder. One block (128 thr) per batch row.
// Context grid read from g_bufB (conv3 output).
// ---------------------------------------------------------------------------
__device__ __forceinline__ float sigmoidf_(float v) { return 1.f / (1.f + expf(-v)); }
__device__ __forceinline__ float softplusf_(float v) {
    return fmaxf(v, 0.f) + log1pf(expf(-fabsf(v)));
}

__global__ void seq_kernel(const float* __restrict__ z,
                           const float* __restrict__ past,
                           const float* __restrict__ ewih, const float* __restrict__ ewhh,
                           const float* __restrict__ ebih, const float* __restrict__ ebhh,
                           const float* __restrict__ dwih, const float* __restrict__ dwhh,
                           const float* __restrict__ dbih, const float* __restrict__ dbhh,
                           const float* __restrict__ w1, const float* __restrict__ b1,
                           const float* __restrict__ w2, const float* __restrict__ b2,
                           float* __restrict__ out) {
    int b = blockIdx.x, tid = threadIdx.x;
    __shared__ __align__(16) float h[32];
    __shared__ float xv[34];
    __shared__ float sgi[96], sgh[96];
    __shared__ float hid[512];
    __shared__ float sls[4];
    __shared__ float y1s[2], y2s[2];

    if (tid < 32) h[tid] = 0.f;
    __syncthreads();

    // ---- encoder GRU over player_past ----
    for (int t = 0; t < TPAST; t++) {
        if (tid < 96) {
            float x0 = past[(b * TPAST + t) * 2];
            float x1 = past[(b * TPAST + t) * 2 + 1];
            float gi = ebih[tid] + x0 * ewih[tid * 2] + x1 * ewih[tid * 2 + 1];
            float gh = ebhh[tid];
            const float* wr = ewhh + tid * 32;
#pragma unroll 8
            for (int k = 0; k < 32; k++) gh += h[k] * wr[k];
            sgi[tid] = gi; sgh[tid] = gh;
        }
        __syncthreads();
        if (tid < 32) {
            float r  = sigmoidf_(sgi[tid] + sgh[tid]);
            float zg = sigmoidf_(sgi[32 + tid] + sgh[32 + tid]);
            float n  = tanhf(sgi[64 + tid] + r * sgh[64 + tid]);
            h[tid] = (1.f - zg) * n + zg * h[tid];
        }
        __syncthreads();
    }

    if (tid == 0) {
        y2s[0] = past[(b * TPAST + 18) * 2]; y2s[1] = past[(b * TPAST + 18) * 2 + 1];
        y1s[0] = past[(b * TPAST + 19) * 2]; y1s[1] = past[(b * TPAST + 19) * 2 + 1];
    }

    float prod0 = 1.f, prod1 = 1.f;
    const float* ctx = g_bufB;

    // ---- decoder ----
    for (int t = 0; t < TFUT; t++) {
        __syncthreads();  // orders y1s/y2s updates from prev step
        if (tid < 32) {
            float q0 = y1s[0], q1 = y1s[1];
            float fyf = fminf(fmaxf(floorf(q0), 0.f), (float)(GHH - 2));
            float fxf = fminf(fmaxf(floorf(q1), 0.f), (float)(GWW - 2));
            float ay = fminf(fmaxf(q0 - fyf, 0.f), 1.f);
            float ax = fminf(fmaxf(q1 - fxf, 0.f), 1.f);
            int fy = (int)fyf, fx = (int)fxf;
            const float* gb = ctx + (((size_t)b * GHH + fy) * GWW + fx) * 32 + tid;
            float tl = gb[0], tr = gb[32], bl = gb[GWW * 32], br = gb[GWW * 32 + 32];
            float top = tl + ax * (tr - tl);
            float bot = bl + ax * (br - bl);
            xv[2 + tid] = top + ay * (bot - top);
            if (tid == 0) { xv[0] = q0; xv[1] = q1; }
        }
        __syncthreads();
        if (tid < 96) {
            float gi = dbih[tid];
            const float* wi = dwih + tid * 34;
#pragma unroll 2
            for (int k = 0; k < 34; k++) gi += xv[k] * wi[k];
            float gh = dbhh[tid];
            const float* wh = dwhh + tid * 32;
#pragma unroll 8
            for (int k = 0; k < 32; k++) gh += h[k] * wh[k];
            sgi[tid] = gi; sgh[tid] = gh;
        }
        __syncthreads();
        if (tid < 32) {
            float r  = sigmoidf_(sgi[tid] + sgh[tid]);
            float zg = sigmoidf_(sgi[32 + tid] + sgh[32 + tid]);
            float n  = tanhf(sgi[64 + tid] + r * sgh[64 + tid]);
            h[tid] = (1.f - zg) * n + zg * h[tid];
        }
        __syncthreads();
        // MLP layer 1: 512 = 128 threads x 4 outputs
#pragma unroll
        for (int j = 0; j < 4; j++) {
            int o = tid + 128 * j;
            float s = b1[o];
            const float4* wr = reinterpret_cast<const float4*>(w1 + o * 32);
            const float4* hv = reinterpret_cast<const float4*>(h);
#pragma unroll
            for (int q = 0; q < 8; q++) {
                float4 wv = wr[q]; float4 hh = hv[q];
                s += wv.x * hh.x + wv.y * hh.y + wv.z * hh.z + wv.w * hh.w;
            }
            hid[o] = s;
        }
        __syncthreads();
        // MLP layer 2: warp w -> output w
        {
            int ww = tid >> 5, lane = tid & 31;
            float p = 0.f;
            const float* wr = w2 + ww * 512;
#pragma unroll
            for (int i = 0; i < 16; i++) {
                int k = lane + 32 * i;
                p += hid[k] * wr[k];
            }
#pragma unroll
            for (int off = 16; off; off >>= 1) p += __shfl_xor_sync(0xffffffffu, p, off);
            if (lane == 0) sls[ww] = p + b2[ww];
        }
        __syncthreads();
        if (tid == 0) {
            float loc0 = sls[0], loc1 = sls[1];
            float s0 = softplusf_(sls[2]);
            float s1 = softplusf_(sls[3]);
            float zt0 = z[(b * TFUT + t) * 2], zt1 = z[(b * TFUT + t) * 2 + 1];
            float yn0 = 2.f * y1s[0] - y2s[0] + loc0 + s0 * zt0;
            float yn1 = 2.f * y1s[1] - y2s[1] + loc1 + s1 * zt1;
            out[(b * TFUT + t) * 2]     = yn0;
            out[(b * TFUT + t) * 2 + 1] = yn1;
            prod0 *= s0; prod1 *= s1;
            y2s[0] = y1s[0]; y2s[1] = y1s[1];
            y1s[0] = yn0;    y1s[1] = yn1;
        }
    }
    if (tid == 0)
        out[BATCH * TFUT * 2 + b] = logf(fabsf(prod0)) + logf(fabsf(prod1));
}

// ---------------------------------------------------------------------------
extern "C" void kernel_launch(void* const* d_in, const int* in_sizes, int n_in,
                              void* d_out, int out_size) {
    const float* z    = (const float*)d_in[0];
    const float* past = (const float*)d_in[1];
    const float* lidar= (const float*)d_in[2];
    const float* c0w  = (const float*)d_in[3];
    const float* c0b  = (const float*)d_in[4];
    const float* c1w  = (const float*)d_in[5];
    const float* c1b  = (const float*)d_in[6];
    const float* c2w  = (const float*)d_in[7];
    const float* c2b  = (const float*)d_in[8];
    const float* c3w  = (const float*)d_in[9];
    const float* c3b  = (const float*)d_in[10];
    const float* ewih = (const float*)d_in[11];
    const float* ewhh = (const float*)d_in[12];
    const float* ebih = (const float*)d_in[13];
    const float* ebhh = (const float*)d_in[14];
    const float* dwih = (const float*)d_in[15];
    const float* dwhh = (const float*)d_in[16];
    const float* dbih = (const float*)d_in[17];
    const float* dbhh = (const float*)d_in[18];
    const float* w1   = (const float*)d_in[19];
    const float* b1   = (const float*)d_in[20];
    const float* w2   = (const float*)d_in[21];
    const float* b2   = (const float*)d_in[22];
    float* out = (float*)d_out;

    cudaFuncSetAttribute(convN_kernel, cudaFuncAttributeMaxDynamicSharedMemorySize,
                         SMEM_IN_BYTES);

    conv0_kernel<<<(BATCH * GHH * GWW + 255) / 256, 256>>>(lidar, c0w, c0b);

    dim3 cgrid((GWW + TILE - 1) / TILE, (GHH + TILE - 1) / TILE, BATCH);
    convN_kernel<<<cgrid, 128, SMEM_IN_BYTES>>>(c1w, c1b, 1); // A -> B
    convN_kernel<<<cgrid, 128, SMEM_IN_BYTES>>>(c2w, c2b, 0); // B -> A
    convN_kernel<<<cgrid, 128, SMEM_IN_BYTES>>>(c3w, c3b, 1); // A -> B

    seq_kernel<<<BATCH, 128>>>(z, past, ewih, ewhh, ebih, ebhh,
                               dwih, dwhh, dbih, dbhh, w1, b1, w2, b2, out);
}

// round 4
// speedup vs baseline: 1.0016x; 1.0016x over previous
#include <cuda_runtime.h>
#include <math.h>

#define BATCH 256
#define GHH 100
#define GWW 100
#define CH 32
#define TPAST 20
#define TFUT 30

// Ping-pong scratch for the conv stack (sanctioned __device__ global scratch).
__device__ __align__(128) float g_bufA[(size_t)BATCH*GHH*GWW*CH];
__device__ __align__(128) float g_bufB[(size_t)BATCH*GHH*GWW*CH];

// ---------------------------------------------------------------------------
// conv0: 2ch -> 32ch, 2x2 kernel, pad (0,1)x(0,1), relu. One thread per pixel.
// ---------------------------------------------------------------------------
__global__ void conv0_kernel(const float* __restrict__ lidar,
                             const float* __restrict__ w,
                             const float* __restrict__ bias) {
    __shared__ __align__(16) float sw[256];
    __shared__ float sb[32];
    int tid = threadIdx.x;
    if (tid < 256) sw[tid] = w[tid];
    if (tid < 32)  sb[tid] = bias[tid];
    __syncthreads();
    int p = blockIdx.x * blockDim.x + tid;
    if (p >= BATCH * GHH * GWW) return;
    int b   = p / (GHH * GWW);
    int rem = p % (GHH * GWW);
    int y = rem / GWW, x = rem % GWW;

    float a[8];
#pragma unroll
    for (int dy = 0; dy < 2; dy++)
#pragma unroll
        for (int dx = 0; dx < 2; dx++) {
            int yy = y + dy, xx = x + dx;
            bool ok = (yy < GHH) && (xx < GWW);
            const float* ip = lidar + ((size_t)(b * GHH + yy) * GWW + xx) * 2;
            a[(dy * 2 + dx) * 2 + 0] = ok ? ip[0] : 0.f;
            a[(dy * 2 + dx) * 2 + 1] = ok ? ip[1] : 0.f;
        }

    float acc[32];
#pragma unroll
    for (int c = 0; c < 32; c++) acc[c] = sb[c];
#pragma unroll
    for (int k = 0; k < 8; k++) {
        float av = a[k];
        const float4* w4 = reinterpret_cast<const float4*>(&sw[k * 32]);
#pragma unroll
        for (int q = 0; q < 8; q++) {
            float4 wv = w4[q];
            acc[4 * q + 0] += av * wv.x;
            acc[4 * q + 1] += av * wv.y;
            acc[4 * q + 2] += av * wv.z;
            acc[4 * q + 3] += av * wv.w;
        }
    }
    float4* op = reinterpret_cast<float4*>(&g_bufA[(size_t)p * 32]);
#pragma unroll
    for (int q = 0; q < 8; q++) {
        float4 v;
        v.x = fmaxf(acc[4 * q + 0], 0.f);
        v.y = fmaxf(acc[4 * q + 1], 0.f);
        v.z = fmaxf(acc[4 * q + 2], 0.f);
        v.w = fmaxf(acc[4 * q + 3], 0.f);
        op[q] = v;
    }
}

// ---------------------------------------------------------------------------
// convN: 32ch -> 32ch, 2x2 kernel, pad (0,1)x(0,1), relu.
// 16x16 pixel tile per block, 128 threads, 2 pixels x 32 channels per thread.
// smem input tile pitch 33 floats -> conflict-free activation loads.
// ---------------------------------------------------------------------------
#define TILE 16
#define SPITCH 33
#define SMEM_IN_BYTES (17 * 17 * SPITCH * 4)

__global__ void convN_kernel(const float* __restrict__ w,
                             const float* __restrict__ bias,
                             int srcIsA) {
    extern __shared__ float s_in[];                 // [17*17][33]
    __shared__ __align__(16) float s_w[4096];       // [4][32][32]
    __shared__ float s_b[32];

    const float* in   = srcIsA ? g_bufA : g_bufB;
    float*       outp = srcIsA ? g_bufB : g_bufA;

    int tid = threadIdx.x;                          // 128
    int b   = blockIdx.z;
    int by  = blockIdx.y * TILE, bx = blockIdx.x * TILE;

    for (int i = tid; i < 1024; i += 128)
        reinterpret_cast<float4*>(s_w)[i] = reinterpret_cast<const float4*>(w)[i];
    if (tid < 32) s_b[tid] = bias[tid];

    // Load 17x17x32 input tile (zero-padded past the grid edge).
    for (int i = tid; i < 289 * 8; i += 128) {
        int pix = i >> 3, j = i & 7;
        int r = pix / 17, c = pix % 17;
        int gy = by + r, gx = bx + c;
        float4 v = make_float4(0.f, 0.f, 0.f, 0.f);
        if (gy < GHH && gx < GWW)
            v = reinterpret_cast<const float4*>(
                    in + ((size_t)(b * GHH + gy) * GWW + gx) * 32)[j];
        float* dp = s_in + pix * SPITCH + j * 4;
        dp[0] = v.x; dp[1] = v.y; dp[2] = v.z; dp[3] = v.w;
    }
    __syncthreads();

    int tx = tid & 15, ty0 = tid >> 4;              // ty0 in 0..7
    float acc0[32], acc1[32];
#pragma unroll
    for (int c = 0; c < 32; c++) { acc0[c] = s_b[c]; acc1[c] = s_b[c]; }

#pragma unroll
    for (int dy = 0; dy < 2; dy++)
#pragma unroll
        for (int dx = 0; dx < 2; dx++) {
            const float* i0 = s_in + ((ty0 + dy) * 17 + tx + dx) * SPITCH;
            const float* i1 = s_in + ((ty0 + 8 + dy) * 17 + tx + dx) * SPITCH;
            const float* wp = s_w + (dy * 2 + dx) * 1024;
#pragma unroll 4
            for (int ci = 0; ci < 32; ci++) {
                float a0 = i0[ci], a1 = i1[ci];
                const float4* w4 = reinterpret_cast<const float4*>(wp + ci * 32);
#pragma unroll
                for (int q = 0; q < 8; q++) {
                    float4 wv = w4[q];
                    acc0[4 * q + 0] += a0 * wv.x; acc0[4 * q + 1] += a0 * wv.y;
                    acc0[4 * q + 2] += a0 * wv.z; acc0[4 * q + 3] += a0 * wv.w;
                    acc1[4 * q + 0] += a1 * wv.x; acc1[4 * q + 1] += a1 * wv.y;
                    acc1[4 * q + 2] += a1 * wv.z; acc1[4 * q + 3] += a1 * wv.w;
                }
            }
        }

    int gx = bx + tx;
    if (gx < GWW) {
        int gy0 = by + ty0;
        if (gy0 < GHH) {
            float4* op = reinterpret_cast<float4*>(
                outp + ((size_t)(b * GHH + gy0) * GWW + gx) * 32);
#pragma unroll
            for (int q = 0; q < 8; q++)
                op[q] = make_float4(fmaxf(acc0[4 * q + 0], 0.f), fmaxf(acc0[4 * q + 1], 0.f),
                                    fmaxf(acc0[4 * q + 2], 0.f), fmaxf(acc0[4 * q + 3], 0.f));
        }
        int gy1 = by + ty0 + 8;
        if (gy1 < GHH) {
            float4* op = reinterpret_cast<float4*>(
                outp + ((size_t)(b * GHH + gy1) * GWW + gx) * 32);
#pragma unroll
            for (int q = 0; q < 8; q++)
                op[q] = make_float4(fmaxf(acc1[4 * q + 0], 0.f), fmaxf(acc1[4 * q + 1], 0.f),
                                    fmaxf(acc1[4 * q + 2], 0.f), fmaxf(acc1[4 * q + 3], 0.f));
        }
    }
}

// ---------------------------------------------------------------------------
// Fused GRU encoder + autoregressive decoder. One block (128 thr) per batch row.
// Context grid read from g_bufB (conv3 output).
// ---------------------------------------------------------------------------
__device__ __forceinline__ float sigmoidf_(float v) { return 1.f / (1.f + expf(-v)); }
__device__ __forceinline__ float softplusf_(float v) {
    return fmaxf(v, 0.f) + log1pf(expf(-fabsf(v)));
}

__global__ void seq_kernel(const float* __restrict__ z,
                           const float* __restrict__ past,
                           const float* __restrict__ ewih, const float* __restrict__ ewhh,
                           const float* __restrict__ ebih, const float* __restrict__ ebhh,
                           const float* __restrict__ dwih, const float* __restrict__ dwhh,
                           const float* __restrict__ dbih, const float* __restrict__ dbhh,
                           const float* __restrict__ w1, const float* __restrict__ b1,
                           const float* __restrict__ w2, const float* __restrict__ b2,
                           float* __restrict__ out) {
    int b = blockIdx.x, tid = threadIdx.x;
    __shared__ __align__(16) float h[32];
    __shared__ float xv[34];
    __shared__ float sgi[96], sgh[96];
    __shared__ float hid[512];
    __shared__ float sls[4];
    __shared__ float y1s[2], y2s[2];

    if (tid < 32) h[tid] = 0.f;
    __syncthreads();

    // ---- encoder GRU over player_past ----
    for (int t = 0; t < TPAST; t++) {
        if (tid < 96) {
            float x0 = past[(b * TPAST + t) * 2];
            float x1 = past[(b * TPAST + t) * 2 + 1];
            float gi = ebih[tid] + x0 * ewih[tid * 2] + x1 * ewih[tid * 2 + 1];
            float gh = ebhh[tid];
            const float* wr = ewhh + tid * 32;
#pragma unroll 8
            for (int k = 0; k < 32; k++) gh += h[k] * wr[k];
            sgi[tid] = gi; sgh[tid] = gh;
        }
        __syncthreads();
        if (tid < 32) {
            float r  = sigmoidf_(sgi[tid] + sgh[tid]);
            float zg = sigmoidf_(sgi[32 + tid] + sgh[32 + tid]);
            float n  = tanhf(sgi[64 + tid] + r * sgh[64 + tid]);
            h[tid] = (1.f - zg) * n + zg * h[tid];
        }
        __syncthreads();
    }

    if (tid == 0) {
        y2s[0] = past[(b * TPAST + 18) * 2]; y2s[1] = past[(b * TPAST + 18) * 2 + 1];
        y1s[0] = past[(b * TPAST + 19) * 2]; y1s[1] = past[(b * TPAST + 19) * 2 + 1];
    }

    float prod0 = 1.f, prod1 = 1.f;
    const float* ctx = g_bufB;

    // ---- decoder ----
    for (int t = 0; t < TFUT; t++) {
        __syncthreads();  // orders y1s/y2s updates from prev step
        if (tid < 32) {
            float q0 = y1s[0], q1 = y1s[1];
            float fyf = fminf(fmaxf(floorf(q0), 0.f), (float)(GHH - 2));
            float fxf = fminf(fmaxf(floorf(q1), 0.f), (float)(GWW - 2));
            float ay = fminf(fmaxf(q0 - fyf, 0.f), 1.f);
            float ax = fminf(fmaxf(q1 - fxf, 0.f), 1.f);
            int fy = (int)fyf, fx = (int)fxf;
            const float* gb = ctx + (((size_t)b * GHH + fy) * GWW + fx) * 32 + tid;
            float tl = gb[0], tr = gb[32], bl = gb[GWW * 32], br = gb[GWW * 32 + 32];
            float top = tl + ax * (tr - tl);
            float bot = bl + ax * (br - bl);
            xv[2 + tid] = top + ay * (bot - top);
            if (tid == 0) { xv[0] = q0; xv[1] = q1; }
        }
        __syncthreads();
        if (tid < 96) {
            float gi = dbih[tid];
            const float* wi = dwih + tid * 34;
#pragma unroll 2
            for (int k = 0; k < 34; k++) gi += xv[k] * wi[k];
            float gh = dbhh[tid];
            const float* wh = dwhh + tid * 32;
#pragma unroll 8
            for (int k = 0; k < 32; k++) gh += h[k] * wh[k];
            sgi[tid] = gi; sgh[tid] = gh;
        }
        __syncthreads();
        if (tid < 32) {
            float r  = sigmoidf_(sgi[tid] + sgh[tid]);
            float zg = sigmoidf_(sgi[32 + tid] + sgh[32 + tid]);
            float n  = tanhf(sgi[64 + tid] + r * sgh[64 + tid]);
            h[tid] = (1.f - zg) * n + zg * h[tid];
        }
        __syncthreads();
        // MLP layer 1: 512 = 128 threads x 4 outputs
#pragma unroll
        for (int j = 0; j < 4; j++) {
            int o = tid + 128 * j;
            float s = b1[o];
            const float4* wr = reinterpret_cast<const float4*>(w1 + o * 32);
            const float4* hv = reinterpret_cast<const float4*>(h);
#pragma unroll
            for (int q = 0; q < 8; q++) {
                float4 wv = wr[q]; float4 hh = hv[q];
                s += wv.x * hh.x + wv.y * hh.y + wv.z * hh.z + wv.w * hh.w;
            }
            hid[o] = s;
        }
        __syncthreads();
        // MLP layer 2: warp w -> output w
        {
            int ww = tid >> 5, lane = tid & 31;
            float p = 0.f;
            const float* wr = w2 + ww * 512;
#pragma unroll
            for (int i = 0; i < 16; i++) {
                int k = lane + 32 * i;
                p += hid[k] * wr[k];
            }
#pragma unroll
            for (int off = 16; off; off >>= 1) p += __shfl_xor_sync(0xffffffffu, p, off);
            if (lane == 0) sls[ww] = p + b2[ww];
        }
        __syncthreads();
        if (tid == 0) {
            float loc0 = sls[0], loc1 = sls[1];
            float s0 = softplusf_(sls[2]);
            float s1 = softplusf_(sls[3]);
            float zt0 = z[(b * TFUT + t) * 2], zt1 = z[(b * TFUT + t) * 2 + 1];
            float yn0 = 2.f * y1s[0] - y2s[0] + loc0 + s0 * zt0;
            float yn1 = 2.f * y1s[1] - y2s[1] + loc1 + s1 * zt1;
            out[(b * TFUT + t) * 2]     = yn0;
            out[(b * TFUT + t) * 2 + 1] = yn1;
            prod0 *= s0; prod1 *= s1;
            y2s[0] = y1s[0]; y2s[1] = y1s[1];
            y1s[0] = yn0;    y1s[1] = yn1;
        }
    }
    if (tid == 0)
        out[BATCH * TFUT * 2 + b] = logf(fabsf(prod0)) + logf(fabsf(prod1));
}

// ---------------------------------------------------------------------------
extern "C" void kernel_launch(void* const* d_in, const int* in_sizes, int n_in,
                              void* d_out, int out_size) {
    const float* z    = (const float*)d_in[0];
    const float* past = (const float*)d_in[1];
    const float* lidar= (const float*)d_in[2];
    const float* c0w  = (const float*)d_in[3];
    const float* c0b  = (const float*)d_in[4];
    const float* c1w  = (const float*)d_in[5];
    const float* c1b  = (const float*)d_in[6];
    const float* c2w  = (const float*)d_in[7];
    const float* c2b  = (const float*)d_in[8];
    const float* c3w  = (const float*)d_in[9];
    const float* c3b  = (const float*)d_in[10];
    const float* ewih = (const float*)d_in[11];
    const float* ewhh = (const float*)d_in[12];
    const float* ebih = (const float*)d_in[13];
    const float* ebhh = (const float*)d_in[14];
    const float* dwih = (const float*)d_in[15];
    const float* dwhh = (const float*)d_in[16];
    const float* dbih = (const float*)d_in[17];
    const float* dbhh = (const float*)d_in[18];
    const float* w1   = (const float*)d_in[19];
    const float* b1   = (const float*)d_in[20];
    const float* w2   = (const float*)d_in[21];
    const float* b2   = (const float*)d_in[22];
    float* out = (float*)d_out;

    cudaFuncSetAttribute(convN_kernel, cudaFuncAttributeMaxDynamicSharedMemorySize,
                         SMEM_IN_BYTES);

    conv0_kernel<<<(BATCH * GHH * GWW + 255) / 256, 256>>>(lidar, c0w, c0b);

    dim3 cgrid((GWW + TILE - 1) / TILE, (GHH + TILE - 1) / TILE, BATCH);
    convN_kernel<<<cgrid, 128, SMEM_IN_BYTES>>>(c1w, c1b, 1); // A -> B
    convN_kernel<<<cgrid, 128, SMEM_IN_BYTES>>>(c2w, c2b, 0); // B -> A
    convN_kernel<<<cgrid, 128, SMEM_IN_BYTES>>>(c3w, c3b, 1); // A -> B

    seq_kernel<<<BATCH, 128>>>(z, past, ewih, ewhh, ebih, ebhh,
                               dwih, dwhh, dbih, dbhh, w1, b1, w2, b2, out);
}

// round 5
// speedup vs baseline: 1.0494x; 1.0477x over previous
#include <cuda_runtime.h>
#include <math.h>

#define BATCH 256
#define GHH 100
#define GWW 100
#define CH 32
#define TPAST 20
#define TFUT 30

// Ping-pong scratch for the conv stack (sanctioned __device__ global scratch).
__device__ __align__(128) float g_bufA[(size_t)BATCH*GHH*GWW*CH];
__device__ __align__(128) float g_bufB[(size_t)BATCH*GHH*GWW*CH];

// ---- packed f32x2 helpers (sm_103a: FFMA2 only reachable via PTX) ----------
__device__ __forceinline__ unsigned long long ffma2(unsigned long long a,
                                                    unsigned long long b,
                                                    unsigned long long c) {
    unsigned long long d;
    asm("fma.rn.f32x2 %0, %1, %2, %3;" : "=l"(d) : "l"(a), "l"(b), "l"(c));
    return d;
}
__device__ __forceinline__ unsigned long long pack2(float x, float y) {
    unsigned long long r;
    asm("mov.b64 %0, {%1, %2};" : "=l"(r) : "f"(x), "f"(y));
    return r;
}
__device__ __forceinline__ float2 unpack2(unsigned long long v) {
    float2 r;
    asm("mov.b64 {%0, %1}, %2;" : "=f"(r.x), "=f"(r.y) : "l"(v));
    return r;
}

// ---------------------------------------------------------------------------
// conv0: 2ch -> 32ch, 2x2 kernel, pad (0,1)x(0,1), relu. One thread per pixel.
// ---------------------------------------------------------------------------
__global__ void conv0_kernel(const float* __restrict__ lidar,
                             const float* __restrict__ w,
                             const float* __restrict__ bias) {
    __shared__ __align__(16) float sw[256];
    __shared__ float sb[32];
    int tid = threadIdx.x;
    if (tid < 256) sw[tid] = w[tid];
    if (tid < 32)  sb[tid] = bias[tid];
    __syncthreads();
    int p = blockIdx.x * blockDim.x + tid;
    if (p >= BATCH * GHH * GWW) return;
    int b   = p / (GHH * GWW);
    int rem = p % (GHH * GWW);
    int y = rem / GWW, x = rem % GWW;

    float a[8];
#pragma unroll
    for (int dy = 0; dy < 2; dy++)
#pragma unroll
        for (int dx = 0; dx < 2; dx++) {
            int yy = y + dy, xx = x + dx;
            bool ok = (yy < GHH) && (xx < GWW);
            const float* ip = lidar + ((size_t)(b * GHH + yy) * GWW + xx) * 2;
            a[(dy * 2 + dx) * 2 + 0] = ok ? ip[0] : 0.f;
            a[(dy * 2 + dx) * 2 + 1] = ok ? ip[1] : 0.f;
        }

    float acc[32];
#pragma unroll
    for (int c = 0; c < 32; c++) acc[c] = sb[c];
#pragma unroll
    for (int k = 0; k < 8; k++) {
        float av = a[k];
        const float4* w4 = reinterpret_cast<const float4*>(&sw[k * 32]);
#pragma unroll
        for (int q = 0; q < 8; q++) {
            float4 wv = w4[q];
            acc[4 * q + 0] += av * wv.x;
            acc[4 * q + 1] += av * wv.y;
            acc[4 * q + 2] += av * wv.z;
            acc[4 * q + 3] += av * wv.w;
        }
    }
    float4* op = reinterpret_cast<float4*>(&g_bufA[(size_t)p * 32]);
#pragma unroll
    for (int q = 0; q < 8; q++) {
        float4 v;
        v.x = fmaxf(acc[4 * q + 0], 0.f);
        v.y = fmaxf(acc[4 * q + 1], 0.f);
        v.z = fmaxf(acc[4 * q + 2], 0.f);
        v.w = fmaxf(acc[4 * q + 3], 0.f);
        op[q] = v;
    }
}

// ---------------------------------------------------------------------------
// convN: 32ch -> 32ch, 2x2 kernel, pad (0,1)x(0,1), relu.
// 16x16 pixel tile per block, 128 threads, 2 pixels x 32 channels per thread.
// Inner product on packed fma.rn.f32x2 (FFMA2): half the issue slots of
// scalar FFMA, identical rounding.
// ---------------------------------------------------------------------------
#define TILE 16
#define SPITCH 33
#define SMEM_IN_BYTES (17 * 17 * SPITCH * 4)

__global__ void convN_kernel(const float* __restrict__ w,
                             const float* __restrict__ bias,
                             int srcIsA) {
    extern __shared__ float s_in[];                 // [17*17][33]
    __shared__ __align__(16) float s_w[4096];       // [4][32ci][32co]
    __shared__ float s_b[32];

    const float* in   = srcIsA ? g_bufA : g_bufB;
    float*       outp = srcIsA ? g_bufB : g_bufA;

    int tid = threadIdx.x;                          // 128
    int b   = blockIdx.z;
    int by  = blockIdx.y * TILE, bx = blockIdx.x * TILE;

    for (int i = tid; i < 1024; i += 128)
        reinterpret_cast<float4*>(s_w)[i] = reinterpret_cast<const float4*>(w)[i];
    if (tid < 32) s_b[tid] = bias[tid];

    // Load 17x17x32 input tile (zero-padded past the grid edge).
    for (int i = tid; i < 289 * 8; i += 128) {
        int pix = i >> 3, j = i & 7;
        int r = pix / 17, c = pix % 17;
        int gy = by + r, gx = bx + c;
        float4 v = make_float4(0.f, 0.f, 0.f, 0.f);
        if (gy < GHH && gx < GWW)
            v = reinterpret_cast<const float4*>(
                    in + ((size_t)(b * GHH + gy) * GWW + gx) * 32)[j];
        float* dp = s_in + pix * SPITCH + j * 4;
        dp[0] = v.x; dp[1] = v.y; dp[2] = v.z; dp[3] = v.w;
    }
    __syncthreads();

    int tx = tid & 15, ty0 = tid >> 4;              // ty0 in 0..7

    unsigned long long acc0[16], acc1[16];          // 16 f32x2 pairs per pixel
#pragma unroll
    for (int p = 0; p < 16; p++) {
        unsigned long long bb = pack2(s_b[2 * p], s_b[2 * p + 1]);
        acc0[p] = bb; acc1[p] = bb;
    }

#pragma unroll
    for (int dy = 0; dy < 2; dy++)
#pragma unroll
        for (int dx = 0; dx < 2; dx++) {
            const float* i0 = s_in + ((ty0 + dy) * 17 + tx + dx) * SPITCH;
            const float* i1 = s_in + ((ty0 + 8 + dy) * 17 + tx + dx) * SPITCH;
            const float* wp = s_w + (dy * 2 + dx) * 1024;
#pragma unroll 4
            for (int ci = 0; ci < 32; ci++) {
                float a0 = i0[ci], a1 = i1[ci];
                unsigned long long a0d = pack2(a0, a0);
                unsigned long long a1d = pack2(a1, a1);
                const ulonglong2* w2 = reinterpret_cast<const ulonglong2*>(wp + ci * 32);
#pragma unroll
                for (int q = 0; q < 8; q++) {
                    ulonglong2 wv = w2[q];
                    acc0[2 * q + 0] = ffma2(a0d, wv.x, acc0[2 * q + 0]);
                    acc0[2 * q + 1] = ffma2(a0d, wv.y, acc0[2 * q + 1]);
                    acc1[2 * q + 0] = ffma2(a1d, wv.x, acc1[2 * q + 0]);
                    acc1[2 * q + 1] = ffma2(a1d, wv.y, acc1[2 * q + 1]);
                }
            }
        }

    int gx = bx + tx;
    if (gx < GWW) {
        int gy0 = by + ty0;
        if (gy0 < GHH) {
            float4* op = reinterpret_cast<float4*>(
                outp + ((size_t)(b * GHH + gy0) * GWW + gx) * 32);
#pragma unroll
            for (int q = 0; q < 8; q++) {
                float2 lo = unpack2(acc0[2 * q]), hi = unpack2(acc0[2 * q + 1]);
                op[q] = make_float4(fmaxf(lo.x, 0.f), fmaxf(lo.y, 0.f),
                                    fmaxf(hi.x, 0.f), fmaxf(hi.y, 0.f));
            }
        }
        int gy1 = by + ty0 + 8;
        if (gy1 < GHH) {
            float4* op = reinterpret_cast<float4*>(
                outp + ((size_t)(b * GHH + gy1) * GWW + gx) * 32);
#pragma unroll
            for (int q = 0; q < 8; q++) {
                float2 lo = unpack2(acc1[2 * q]), hi = unpack2(acc1[2 * q + 1]);
                op[q] = make_float4(fmaxf(lo.x, 0.f), fmaxf(lo.y, 0.f),
                                    fmaxf(hi.x, 0.f), fmaxf(hi.y, 0.f));
            }
        }
    }
}

// ---------------------------------------------------------------------------
// Fused GRU encoder + autoregressive decoder. One block (128 thr) per batch row.
// Context grid read from g_bufB (conv3 output).
// ---------------------------------------------------------------------------
__device__ __forceinline__ float sigmoidf_(float v) { return 1.f / (1.f + expf(-v)); }
__device__ __forceinline__ float softplusf_(float v) {
    return fmaxf(v, 0.f) + log1pf(expf(-fabsf(v)));
}

__global__ void seq_kernel(const float* __restrict__ z,
                           const float* __restrict__ past,
                           const float* __restrict__ ewih, const float* __restrict__ ewhh,
                           const float* __restrict__ ebih, const float* __restrict__ ebhh,
                           const float* __restrict__ dwih, const float* __restrict__ dwhh,
                           const float* __restrict__ dbih, const float* __restrict__ dbhh,
                           const float* __restrict__ w1, const float* __restrict__ b1,
                           const float* __restrict__ w2, const float* __restrict__ b2,
                           float* __restrict__ out) {
    int b = blockIdx.x, tid = threadIdx.x;
    __shared__ __align__(16) float h[32];
    __shared__ float xv[34];
    __shared__ float sgi[96], sgh[96];
    __shared__ float hid[512];
    __shared__ float sls[4];
    __shared__ float y1s[2], y2s[2];

    if (tid < 32) h[tid] = 0.f;
    __syncthreads();

    // ---- encoder GRU over player_past ----
    for (int t = 0; t < TPAST; t++) {
        if (tid < 96) {
            float x0 = past[(b * TPAST + t) * 2];
            float x1 = past[(b * TPAST + t) * 2 + 1];
            float gi = ebih[tid] + x0 * ewih[tid * 2] + x1 * ewih[tid * 2 + 1];
            float gh = ebhh[tid];
            const float* wr = ewhh + tid * 32;
#pragma unroll 8
            for (int k = 0; k < 32; k++) gh += h[k] * wr[k];
            sgi[tid] = gi; sgh[tid] = gh;
        }
        __syncthreads();
        if (tid < 32) {
            float r  = sigmoidf_(sgi[tid] + sgh[tid]);
            float zg = sigmoidf_(sgi[32 + tid] + sgh[32 + tid]);
            float n  = tanhf(sgi[64 + tid] + r * sgh[64 + tid]);
            h[tid] = (1.f - zg) * n + zg * h[tid];
        }
        __syncthreads();
    }

    if (tid == 0) {
        y2s[0] = past[(b * TPAST + 18) * 2]; y2s[1] = past[(b * TPAST + 18) * 2 + 1];
        y1s[0] = past[(b * TPAST + 19) * 2]; y1s[1] = past[(b * TPAST + 19) * 2 + 1];
    }

    float prod0 = 1.f, prod1 = 1.f;
    const float* ctx = g_bufB;

    // ---- decoder ----
    for (int t = 0; t < TFUT; t++) {
        __syncthreads();  // orders y1s/y2s updates from prev step
        if (tid < 32) {
            float q0 = y1s[0], q1 = y1s[1];
            float fyf = fminf(fmaxf(floorf(q0), 0.f), (float)(GHH - 2));
            float fxf = fminf(fmaxf(floorf(q1), 0.f), (float)(GWW - 2));
            float ay = fminf(fmaxf(q0 - fyf, 0.f), 1.f);
            float ax = fminf(fmaxf(q1 - fxf, 0.f), 1.f);
            int fy = (int)fyf, fx = (int)fxf;
            const float* gb = ctx + (((size_t)b * GHH + fy) * GWW + fx) * 32 + tid;
            float tl = gb[0], tr = gb[32], bl = gb[GWW * 32], br = gb[GWW * 32 + 32];
            float top = tl + ax * (tr - tl);
            float bot = bl + ax * (br - bl);
            xv[2 + tid] = top + ay * (bot - top);
            if (tid == 0) { xv[0] = q0; xv[1] = q1; }
        }
        __syncthreads();
        if (tid < 96) {
            float gi = dbih[tid];
            const float* wi = dwih + tid * 34;
#pragma unroll 2
            for (int k = 0; k < 34; k++) gi += xv[k] * wi[k];
            float gh = dbhh[tid];
            const float* wh = dwhh + tid * 32;
#pragma unroll 8
            for (int k = 0; k < 32; k++) gh += h[k] * wh[k];
            sgi[tid] = gi; sgh[tid] = gh;
        }
        __syncthreads();
        if (tid < 32) {
            float r  = sigmoidf_(sgi[tid] + sgh[tid]);
            float zg = sigmoidf_(sgi[32 + tid] + sgh[32 + tid]);
            float n  = tanhf(sgi[64 + tid] + r * sgh[64 + tid]);
            h[tid] = (1.f - zg) * n + zg * h[tid];
        }
        __syncthreads();
        // MLP layer 1: 512 = 128 threads x 4 outputs
#pragma unroll
        for (int j = 0; j < 4; j++) {
            int o = tid + 128 * j;
            float s = b1[o];
            const float4* wr = reinterpret_cast<const float4*>(w1 + o * 32);
            const float4* hv = reinterpret_cast<const float4*>(h);
#pragma unroll
            for (int q = 0; q < 8; q++) {
                float4 wv = wr[q]; float4 hh = hv[q];
                s += wv.x * hh.x + wv.y * hh.y + wv.z * hh.z + wv.w * hh.w;
            }
            hid[o] = s;
        }
        __syncthreads();
        // MLP layer 2: warp w -> output w
        {
            int ww = tid >> 5, lane = tid & 31;
            float p = 0.f;
            const float* wr = w2 + ww * 512;
#pragma unroll
            for (int i = 0; i < 16; i++) {
                int k = lane + 32 * i;
                p += hid[k] * wr[k];
            }
#pragma unroll
            for (int off = 16; off; off >>= 1) p += __shfl_xor_sync(0xffffffffu, p, off);
            if (lane == 0) sls[ww] = p + b2[ww];
        }
        __syncthreads();
        if (tid == 0) {
            float loc0 = sls[0], loc1 = sls[1];
            float s0 = softplusf_(sls[2]);
            float s1 = softplusf_(sls[3]);
            float zt0 = z[(b * TFUT + t) * 2], zt1 = z[(b * TFUT + t) * 2 + 1];
            float yn0 = 2.f * y1s[0] - y2s[0] + loc0 + s0 * zt0;
            float yn1 = 2.f * y1s[1] - y2s[1] + loc1 + s1 * zt1;
            out[(b * TFUT + t) * 2]     = yn0;
            out[(b * TFUT + t) * 2 + 1] = yn1;
            prod0 *= s0; prod1 *= s1;
            y2s[0] = y1s[0]; y2s[1] = y1s[1];
            y1s[0] = yn0;    y1s[1] = yn1;
        }
    }
    if (tid == 0)
        out[BATCH * TFUT * 2 + b] = logf(fabsf(prod0)) + logf(fabsf(prod1));
}

// ---------------------------------------------------------------------------
extern "C" void kernel_launch(void* const* d_in, const int* in_sizes, int n_in,
                              void* d_out, int out_size) {
    const float* z    = (const float*)d_in[0];
    const float* past = (const float*)d_in[1];
    const float* lidar= (const float*)d_in[2];
    const float* c0w  = (const float*)d_in[3];
    const float* c0b  = (const float*)d_in[4];
    const float* c1w  = (const float*)d_in[5];
    const float* c1b  = (const float*)d_in[6];
    const float* c2w  = (const float*)d_in[7];
    const float* c2b  = (const float*)d_in[8];
    const float* c3w  = (const float*)d_in[9];
    const float* c3b  = (const float*)d_in[10];
    const float* ewih = (const float*)d_in[11];
    const float* ewhh = (const float*)d_in[12];
    const float* ebih = (const float*)d_in[13];
    const float* ebhh = (const float*)d_in[14];
    const float* dwih = (const float*)d_in[15];
    const float* dwhh = (const float*)d_in[16];
    const float* dbih = (const float*)d_in[17];
    const float* dbhh = (const float*)d_in[18];
    const float* w1   = (const float*)d_in[19];
    const float* b1   = (const float*)d_in[20];
    const float* w2   = (const float*)d_in[21];
    const float* b2   = (const float*)d_in[22];
    float* out = (float*)d_out;

    cudaFuncSetAttribute(convN_kernel, cudaFuncAttributeMaxDynamicSharedMemorySize,
                         SMEM_IN_BYTES);

    conv0_kernel<<<(BATCH * GHH * GWW + 255) / 256, 256>>>(lidar, c0w, c0b);

    dim3 cgrid((GWW + TILE - 1) / TILE, (GHH + TILE - 1) / TILE, BATCH);
    convN_kernel<<<cgrid, 128, SMEM_IN_BYTES>>>(c1w, c1b, 1); // A -> B
    convN_kernel<<<cgrid, 128, SMEM_IN_BYTES>>>(c2w, c2b, 0); // B -> A
    convN_kernel<<<cgrid, 128, SMEM_IN_BYTES>>>(c3w, c3b, 1); // A -> B

    seq_kernel<<<BATCH, 128>>>(z, past, ewih, ewhh, ebih, ebhh,
                               dwih, dwhh, dbih, dbhh, w1, b1, w2, b2, out);
}

// round 7
// speedup vs baseline: 1.3186x; 1.2565x over previous
#include <cuda_runtime.h>
#include <math.h>
#include <stdint.h>

#define BATCH 256
#define GHH 100
#define GWW 100
#define CH 32
#define TPAST 20
#define TFUT 30
#define NPIX (GHH * GWW)

// Ping-pong scratch for the conv stack (sanctioned __device__ global scratch).
__device__ __align__(128) float g_bufA[(size_t)BATCH*NPIX*CH];
__device__ __align__(128) float g_bufB[(size_t)BATCH*NPIX*CH];

// ---------------------------------------------------------------------------
// conv0: 2ch -> 32ch, 2x2 kernel, pad (0,1)x(0,1), relu. One thread per pixel.
// ---------------------------------------------------------------------------
__global__ void conv0_kernel(const float* __restrict__ lidar,
                             const float* __restrict__ w,
                             const float* __restrict__ bias) {
    __shared__ __align__(16) float sw[256];
    __shared__ float sb[32];
    int tid = threadIdx.x;
    if (tid < 256) sw[tid] = w[tid];
    if (tid < 32)  sb[tid] = bias[tid];
    __syncthreads();
    int p = blockIdx.x * blockDim.x + tid;
    if (p >= BATCH * NPIX) return;
    int b   = p / NPIX;
    int rem = p % NPIX;
    int y = rem / GWW, x = rem % GWW;

    float a[8];
#pragma unroll
    for (int dy = 0; dy < 2; dy++)
#pragma unroll
        for (int dx = 0; dx < 2; dx++) {
            int yy = y + dy, xx = x + dx;
            bool ok = (yy < GHH) && (xx < GWW);
            const float* ip = lidar + ((size_t)(b * GHH + yy) * GWW + xx) * 2;
            a[(dy * 2 + dx) * 2 + 0] = ok ? ip[0] : 0.f;
            a[(dy * 2 + dx) * 2 + 1] = ok ? ip[1] : 0.f;
        }

    float acc[32];
#pragma unroll
    for (int c = 0; c < 32; c++) acc[c] = sb[c];
#pragma unroll
    for (int k = 0; k < 8; k++) {
        float av = a[k];
        const float4* w4 = reinterpret_cast<const float4*>(&sw[k * 32]);
#pragma unroll
        for (int q = 0; q < 8; q++) {
            float4 wv = w4[q];
            acc[4 * q + 0] += av * wv.x;
            acc[4 * q + 1] += av * wv.y;
            acc[4 * q + 2] += av * wv.z;
            acc[4 * q + 3] += av * wv.w;
        }
    }
    float4* op = reinterpret_cast<float4*>(&g_bufA[(size_t)p * 32]);
#pragma unroll
    for (int q = 0; q < 8; q++) {
        float4 v;
        v.x = fmaxf(acc[4 * q + 0], 0.f);
        v.y = fmaxf(acc[4 * q + 1], 0.f);
        v.z = fmaxf(acc[4 * q + 2], 0.f);
        v.w = fmaxf(acc[4 * q + 3], 0.f);
        op[q] = v;
    }
}

// ---------------------------------------------------------------------------
// convM: 32ch -> 32ch 2x2 conv as warp-level mma.sync tf32 GEMM with 3xTF32
// error compensation (D = Ah*Bh + Ah*Bl + Al*Bh; residuals tf32-truncated).
// CTA = 128-pixel strip of one image; warp computes 32 pixels x 32 ch.
// A operand is the input strip shifted by tap offset {0,1,GWW,GWW+1};
// dx-wrap rows (x == GWW-1) zeroed at fragment load.
// ---------------------------------------------------------------------------
#define SPA 36               // strip pitch (floats): A-frag LDS conflict-free
#define SPB 40               // weight pitch (floats): B-frag LDS conflict-free
#define OFF_S0 0
#define OFF_S1 (129 * SPA)
#define OFF_W  (2 * 129 * SPA)
#define OFF_BI (OFF_W + 128 * SPB)
#define CM_SMEM ((OFF_BI + 32) * 4)

#define MMA_TF32(C, A, B0, B1)                                              \
    asm volatile("mma.sync.aligned.m16n8k8.row.col.f32.tf32.tf32.f32 "      \
                 "{%0,%1,%2,%3}, {%4,%5,%6,%7}, {%8,%9}, {%0,%1,%2,%3};"    \
                 : "+f"(C[0]), "+f"(C[1]), "+f"(C[2]), "+f"(C[3])           \
                 : "r"(A[0]), "r"(A[1]), "r"(A[2]), "r"(A[3]),              \
                   "r"(B0), "r"(B1))

__device__ __forceinline__ uint32_t tf32h(float v) {
    return __float_as_uint(v) & 0xFFFFE000u;
}
__device__ __forceinline__ uint32_t tf32l(float v, uint32_t h) {
    return __float_as_uint(v - __uint_as_float(h)) & 0xFFFFE000u;
}

__global__ void __launch_bounds__(128) convM_kernel(const float* __restrict__ w,
                                                    const float* __restrict__ bias,
                                                    int srcIsA) {
    extern __shared__ float smf[];
    const float* in   = srcIsA ? g_bufA : g_bufB;
    float*       outp = srcIsA ? g_bufB : g_bufA;

    int tid = threadIdx.x;
    int b   = blockIdx.y;
    int p0  = blockIdx.x * 128;

    // ---- weights [k=128][n=32] (raw fp32) + bias ----
    for (int i = tid; i < 4096; i += 128) {
        int k = i >> 5, n = i & 31;
        smf[OFF_W + k * SPB + n] = w[i];
    }
    if (tid < 32) smf[OFF_BI + tid] = bias[tid];

    // ---- two 129-pixel input strips (rows p0.. and p0+GWW..), zero-clamped ----
    const float4* inb = reinterpret_cast<const float4*>(in + (size_t)b * NPIX * 32);
    for (int i = tid; i < 258; i += 128) {
        int st = (i >= 129);
        int r  = st ? i - 129 : i;
        int gp = p0 + r + (st ? GWW : 0);
        float4* dst = reinterpret_cast<float4*>(smf + (st ? OFF_S1 : OFF_S0) + r * SPA);
        if (gp < NPIX) {
            const float4* src = inb + (size_t)gp * 8;
#pragma unroll
            for (int j = 0; j < 8; j++) dst[j] = src[j];
        } else {
            float4 zz = make_float4(0.f, 0.f, 0.f, 0.f);
#pragma unroll
            for (int j = 0; j < 8; j++) dst[j] = zz;
        }
    }
    __syncthreads();

    int lane = tid & 31, wid = tid >> 5;
    int g = lane >> 2, tg = lane & 3;
    int m_warp = wid * 32;

    int  R[4];
    bool wr[4];
#pragma unroll
    for (int i = 0; i < 4; i++) {
        R[i]  = m_warp + g + i * 8;
        wr[i] = (((p0 + R[i]) % GWW) == (GWW - 1));
    }

    float acc[2][4][4];
#pragma unroll
    for (int mt = 0; mt < 2; mt++)
#pragma unroll
        for (int n = 0; n < 4; n++)
#pragma unroll
            for (int q = 0; q < 4; q++) acc[mt][n][q] = 0.f;

    for (int tap = 0; tap < 4; tap++) {
        const float* sp = smf + ((tap & 2) ? OFF_S1 : OFF_S0);
        int dx = tap & 1;
#pragma unroll
        for (int k = 0; k < 4; k++) {
            uint32_t AH[2][4], AL[2][4];
#pragma unroll
            for (int i = 0; i < 4; i++) {
                const float* ap = sp + (R[i] + dx) * SPA + k * 8 + tg;
                bool z = dx && wr[i];
                float v0 = z ? 0.f : ap[0];
                float v1 = z ? 0.f : ap[4];
                uint32_t h0 = tf32h(v0), l0 = tf32l(v0, h0);
                uint32_t h1 = tf32h(v1), l1 = tf32l(v1, h1);
                int mt = i >> 1, rr = i & 1;
                AH[mt][rr]     = h0; AH[mt][rr + 2] = h1;
                AL[mt][rr]     = l0; AL[mt][rr + 2] = l1;
            }
            const float* bp = smf + OFF_W + (tap * 32 + k * 8 + tg) * SPB + g;
#pragma unroll
            for (int n = 0; n < 4; n++) {
                float b0 = bp[n * 8];
                float b1 = bp[n * 8 + 4 * SPB];
                uint32_t bh0 = tf32h(b0), bl0 = tf32l(b0, bh0);
                uint32_t bh1 = tf32h(b1), bl1 = tf32l(b1, bh1);
#pragma unroll
                for (int mt = 0; mt < 2; mt++) {
                    MMA_TF32(acc[mt][n], AH[mt], bh0, bh1);
                    MMA_TF32(acc[mt][n], AH[mt], bl0, bl1);
                    MMA_TF32(acc[mt][n], AL[mt], bh0, bh1);
                }
            }
        }
    }

    // ---- epilogue: bias + relu, float2 stores ----
    const float* sbias = smf + OFF_BI;
#pragma unroll
    for (int mt = 0; mt < 2; mt++) {
        int pr0 = p0 + m_warp + mt * 16 + g;
#pragma unroll
        for (int half = 0; half < 2; half++) {
            int pp = pr0 + half * 8;
            if (pp < NPIX) {
                float* op = outp + ((size_t)b * NPIX + pp) * 32;
#pragma unroll
                for (int n = 0; n < 4; n++) {
                    int col = n * 8 + tg * 2;
                    float2 v;
                    v.x = fmaxf(acc[mt][n][half * 2 + 0] + sbias[col],     0.f);
                    v.y = fmaxf(acc[mt][n][half * 2 + 1] + sbias[col + 1], 0.f);
                    *reinterpret_cast<float2*>(op + col) = v;
                }
            }
        }
    }
}

// ---------------------------------------------------------------------------
// Fused GRU encoder + autoregressive decoder. One block (128 thr) per batch row.
// Context grid read from g_bufB (conv3 output).
// ---------------------------------------------------------------------------
__device__ __forceinline__ float sigmoidf_(float v) { return 1.f / (1.f + expf(-v)); }
__device__ __forceinline__ float softplusf_(float v) {
    return fmaxf(v, 0.f) + log1pf(expf(-fabsf(v)));
}

__global__ void seq_kernel(const float* __restrict__ z,
                           const float* __restrict__ past,
                           const float* __restrict__ ewih, const float* __restrict__ ewhh,
                           const float* __restrict__ ebih, const float* __restrict__ ebhh,
                           const float* __restrict__ dwih, const float* __restrict__ dwhh,
                           const float* __restrict__ dbih, const float* __restrict__ dbhh,
                           const float* __restrict__ w1, const float* __restrict__ b1,
                           const float* __restrict__ w2, const float* __restrict__ b2,
                           float* __restrict__ out) {
    int b = blockIdx.x, tid = threadIdx.x;
    __shared__ __align__(16) float h[32];
    __shared__ float xv[34];
    __shared__ float sgi[96], sgh[96];
    __shared__ float hid[512];
    __shared__ float sls[4];
    __shared__ float y1s[2], y2s[2];

    if (tid < 32) h[tid] = 0.f;
    __syncthreads();

    for (int t = 0; t < TPAST; t++) {
        if (tid < 96) {
            float x0 = past[(b * TPAST + t) * 2];
            float x1 = past[(b * TPAST + t) * 2 + 1];
            float gi = ebih[tid] + x0 * ewih[tid * 2] + x1 * ewih[tid * 2 + 1];
            float gh = ebhh[tid];
            const float* wrp = ewhh + tid * 32;
#pragma unroll 8
            for (int k = 0; k < 32; k++) gh += h[k] * wrp[k];
            sgi[tid] = gi; sgh[tid] = gh;
        }
        __syncthreads();
        if (tid < 32) {
            float rr = sigmoidf_(sgi[tid] + sgh[tid]);
            float zg = sigmoidf_(sgi[32 + tid] + sgh[32 + tid]);
            float n  = tanhf(sgi[64 + tid] + rr * sgh[64 + tid]);
            h[tid] = (1.f - zg) * n + zg * h[tid];
        }
        __syncthreads();
    }

    if (tid == 0) {
        y2s[0] = past[(b * TPAST + 18) * 2]; y2s[1] = past[(b * TPAST + 18) * 2 + 1];
        y1s[0] = past[(b * TPAST + 19) * 2]; y1s[1] = past[(b * TPAST + 19) * 2 + 1];
    }

    float prod0 = 1.f, prod1 = 1.f;
    const float* ctx = g_bufB;

    for (int t = 0; t < TFUT; t++) {
        __syncthreads();
        if (tid < 32) {
            float q0 = y1s[0], q1 = y1s[1];
            float fyf = fminf(fmaxf(floorf(q0), 0.f), (float)(GHH - 2));
            float fxf = fminf(fmaxf(floorf(q1), 0.f), (float)(GWW - 2));
            float ay = fminf(fmaxf(q0 - fyf, 0.f), 1.f);
            float ax = fminf(fmaxf(q1 - fxf, 0.f), 1.f);
            int fy = (int)fyf, fx = (int)fxf;
            const float* gb = ctx + (((size_t)b * GHH + fy) * GWW + fx) * 32 + tid;
            float tl = gb[0], tr = gb[32], bl = gb[GWW * 32], br = gb[GWW * 32 + 32];
            float top = tl + ax * (tr - tl);
            float bot = bl + ax * (br - bl);
            xv[2 + tid] = top + ay * (bot - top);
            if (tid == 0) { xv[0] = q0; xv[1] = q1; }
        }
        __syncthreads();
        if (tid < 96) {
            float gi = dbih[tid];
            const float* wi = dwih + tid * 34;
#pragma unroll 2
            for (int k = 0; k < 34; k++) gi += xv[k] * wi[k];
            float gh = dbhh[tid];
            const float* wh = dwhh + tid * 32;
#pragma unroll 8
            for (int k = 0; k < 32; k++) gh += h[k] * wh[k];
            sgi[tid] = gi; sgh[tid] = gh;
        }
        __syncthreads();
        if (tid < 32) {
            float rr = sigmoidf_(sgi[tid] + sgh[tid]);
            float zg = sigmoidf_(sgi[32 + tid] + sgh[32 + tid]);
            float n  = tanhf(sgi[64 + tid] + rr * sgh[64 + tid]);
            h[tid] = (1.f - zg) * n + zg * h[tid];
        }
        __syncthreads();
#pragma unroll
        for (int j = 0; j < 4; j++) {
            int o = tid + 128 * j;
            float s = b1[o];
            const float4* wrp = reinterpret_cast<const float4*>(w1 + o * 32);
            const float4* hv = reinterpret_cast<const float4*>(h);
#pragma unroll
            for (int q = 0; q < 8; q++) {
                float4 wv = wrp[q]; float4 hh = hv[q];
                s += wv.x * hh.x + wv.y * hh.y + wv.z * hh.z + wv.w * hh.w;
            }
            hid[o] = s;
        }
        __syncthreads();
        {
            int ww = tid >> 5, lane = tid & 31;
            float pq = 0.f;
            const float* wrp = w2 + ww * 512;
#pragma unroll
            for (int i = 0; i < 16; i++) {
                int k = lane + 32 * i;
                pq += hid[k] * wrp[k];
            }
#pragma unroll
            for (int off = 16; off; off >>= 1) pq += __shfl_xor_sync(0xffffffffu, pq, off);
            if (lane == 0) sls[ww] = pq + b2[ww];
        }
        __syncthreads();
        if (tid == 0) {
            float loc0 = sls[0], loc1 = sls[1];
            float s0 = softplusf_(sls[2]);
            float s1 = softplusf_(sls[3]);
            float zt0 = z[(b * TFUT + t) * 2], zt1 = z[(b * TFUT + t) * 2 + 1];
            float yn0 = 2.f * y1s[0] - y2s[0] + loc0 + s0 * zt0;
            float yn1 = 2.f * y1s[1] - y2s[1] + loc1 + s1 * zt1;
            out[(b * TFUT + t) * 2]     = yn0;
            out[(b * TFUT + t) * 2 + 1] = yn1;
            prod0 *= s0; prod1 *= s1;
            y2s[0] = y1s[0]; y2s[1] = y1s[1];
            y1s[0] = yn0;    y1s[1] = yn1;
        }
    }
    if (tid == 0)
        out[BATCH * TFUT * 2 + b] = logf(fabsf(prod0)) + logf(fabsf(prod1));
}

// ---------------------------------------------------------------------------
extern "C" void kernel_launch(void* const* d_in, const int* in_sizes, int n_in,
                              void* d_out, int out_size) {
    const float* z    = (const float*)d_in[0];
    const float* past = (const float*)d_in[1];
    const float* lidar= (const float*)d_in[2];
    const float* c0w  = (const float*)d_in[3];
    const float* c0b  = (const float*)d_in[4];
    const float* c1w  = (const float*)d_in[5];
    const float* c1b  = (const float*)d_in[6];
    const float* c2w  = (const float*)d_in[7];
    const float* c2b  = (const float*)d_in[8];
    const float* c3w  = (const float*)d_in[9];
    const float* c3b  = (const float*)d_in[10];
    const float* ewih = (const float*)d_in[11];
    const float* ewhh = (const float*)d_in[12];
    const float* ebih = (const float*)d_in[13];
    const float* ebhh = (const float*)d_in[14];
    const float* dwih = (const float*)d_in[15];
    const float* dwhh = (const float*)d_in[16];
    const float* dbih = (const float*)d_in[17];
    const float* dbhh = (const float*)d_in[18];
    const float* w1   = (const float*)d_in[19];
    const float* b1   = (const float*)d_in[20];
    const float* w2   = (const float*)d_in[21];
    const float* b2   = (const float*)d_in[22];
    float* out = (float*)d_out;

    cudaFuncSetAttribute(convM_kernel, cudaFuncAttributeMaxDynamicSharedMemorySize,
                         CM_SMEM);

    conv0_kernel<<<(BATCH * NPIX + 255) / 256, 256>>>(lidar, c0w, c0b);

    dim3 cg((NPIX + 127) / 128, BATCH);
    convM_kernel<<<cg, 128, CM_SMEM>>>(c1w, c1b, 1); // A -> B
    convM_kernel<<<cg, 128, CM_SMEM>>>(c2w, c2b, 0); // B -> A
    convM_kernel<<<cg, 128, CM_SMEM>>>(c3w, c3b, 1); // A -> B

    seq_kernel<<<BATCH, 128>>>(z, past, ewih, ewhh, ebih, ebhh,
                               dwih, dwhh, dbih, dbhh, w1, b1, w2, b2, out);
}

// round 8
// speedup vs baseline: 1.5231x; 1.1550x over previous
#include <cuda_runtime.h>
#include <math.h>
#include <stdint.h>

#define BATCH 256
#define GHH 100
#define GWW 100
#define CH 32
#define TPAST 20
#define TFUT 30
#define NPIX (GHH * GWW)

// Ping-pong scratch for the conv stack (sanctioned __device__ global scratch).
__device__ __align__(128) float g_bufA[(size_t)BATCH*NPIX*CH];
__device__ __align__(128) float g_bufB[(size_t)BATCH*NPIX*CH];

// ---------------------------------------------------------------------------
// conv0: 2ch -> 32ch, 2x2 kernel, pad (0,1)x(0,1), relu. One thread per pixel.
// ---------------------------------------------------------------------------
__global__ void conv0_kernel(const float* __restrict__ lidar,
                             const float* __restrict__ w,
                             const float* __restrict__ bias) {
    __shared__ __align__(16) float sw[256];
    __shared__ float sb[32];
    int tid = threadIdx.x;
    if (tid < 256) sw[tid] = w[tid];
    if (tid < 32)  sb[tid] = bias[tid];
    __syncthreads();
    int p = blockIdx.x * blockDim.x + tid;
    if (p >= BATCH * NPIX) return;
    int b   = p / NPIX;
    int rem = p % NPIX;
    int y = rem / GWW, x = rem % GWW;

    float a[8];
#pragma unroll
    for (int dy = 0; dy < 2; dy++)
#pragma unroll
        for (int dx = 0; dx < 2; dx++) {
            int yy = y + dy, xx = x + dx;
            bool ok = (yy < GHH) && (xx < GWW);
            const float* ip = lidar + ((size_t)(b * GHH + yy) * GWW + xx) * 2;
            a[(dy * 2 + dx) * 2 + 0] = ok ? ip[0] : 0.f;
            a[(dy * 2 + dx) * 2 + 1] = ok ? ip[1] : 0.f;
        }

    float acc[32];
#pragma unroll
    for (int c = 0; c < 32; c++) acc[c] = sb[c];
#pragma unroll
    for (int k = 0; k < 8; k++) {
        float av = a[k];
        const float4* w4 = reinterpret_cast<const float4*>(&sw[k * 32]);
#pragma unroll
        for (int q = 0; q < 8; q++) {
            float4 wv = w4[q];
            acc[4 * q + 0] += av * wv.x;
            acc[4 * q + 1] += av * wv.y;
            acc[4 * q + 2] += av * wv.z;
            acc[4 * q + 3] += av * wv.w;
        }
    }
    float4* op = reinterpret_cast<float4*>(&g_bufA[(size_t)p * 32]);
#pragma unroll
    for (int q = 0; q < 8; q++) {
        float4 v;
        v.x = fmaxf(acc[4 * q + 0], 0.f);
        v.y = fmaxf(acc[4 * q + 1], 0.f);
        v.z = fmaxf(acc[4 * q + 2], 0.f);
        v.w = fmaxf(acc[4 * q + 3], 0.f);
        op[q] = v;
    }
}

// ---------------------------------------------------------------------------
// convM: 32ch -> 32ch 2x2 conv as warp-level mma.sync bf16 m16n8k16 GEMM with
// 3-term compensation (D = Ah*Bh + Al*Bh + Ah*Bl). hi/lo conversion hoisted to
// smem tile load; inner loop is pure LDS.32 + HMMA, bank-conflict-free pitches.
// CTA = 128-pixel strip; warp = 32 pixels x 32 ch. One combined 230-pixel
// strip covers all 4 tap shifts {0,1,GWW,GWW+1}; dx-wrap rows zeroed at frag
// load via predicates.
// ---------------------------------------------------------------------------
#define APITCH 20                 // uint32 words per pixel (16 pairs + pad)
#define BPITCH 68                 // uint32 words per out-channel (64 pairs + pad)
#define NSTRIP 232
#define OFF_AH 0
#define OFF_AL (NSTRIP * APITCH)
#define OFF_BH (2 * NSTRIP * APITCH)
#define OFF_BL (OFF_BH + 32 * BPITCH)
#define OFF_BI (OFF_BL + 32 * BPITCH)
#define CM_WORDS (OFF_BI + 32)
#define CM_SMEM (CM_WORDS * 4)

#define MMA_BF16(C, A, B0, B1)                                               \
    asm volatile("mma.sync.aligned.m16n8k16.row.col.f32.bf16.bf16.f32 "      \
                 "{%0,%1,%2,%3}, {%4,%5,%6,%7}, {%8,%9}, {%0,%1,%2,%3};"     \
                 : "+f"(C[0]), "+f"(C[1]), "+f"(C[2]), "+f"(C[3])            \
                 : "r"(A[0]), "r"(A[1]), "r"(A[2]), "r"(A[3]),               \
                   "r"(B0), "r"(B1))

// pack (lo -> bits[15:0], hi -> bits[31:16])
__device__ __forceinline__ uint32_t bf16x2_of(float lo, float hi) {
    uint32_t r;
    asm("cvt.rn.bf16x2.f32 %0, %1, %2;" : "=r"(r) : "f"(hi), "f"(lo));
    return r;
}
__device__ __forceinline__ float2 bf16x2_to_f2(uint32_t u) {
    float2 r;
    r.x = __uint_as_float(u << 16);
    r.y = __uint_as_float(u & 0xFFFF0000u);
    return r;
}

__global__ void __launch_bounds__(128) convM_kernel(const float* __restrict__ w,
                                                    const float* __restrict__ bias,
                                                    int srcIsA) {
    extern __shared__ uint32_t smu[];
    const float* in   = srcIsA ? g_bufA : g_bufB;
    float*       outp = srcIsA ? g_bufB : g_bufA;

    int tid = threadIdx.x;
    int b   = blockIdx.y;
    int p0  = blockIdx.x * 128;

    // ---- weights -> bf16x2 hi/lo pairs: sB[oc][kpair] ----
    for (int i = tid; i < 2048; i += 128) {
        int n = i & 31, j = i >> 5;                  // j = k-pair 0..63
        float v0 = w[(2 * j) * 32 + n];
        float v1 = w[(2 * j + 1) * 32 + n];
        uint32_t h = bf16x2_of(v0, v1);
        float2 hf = bf16x2_to_f2(h);
        uint32_t l = bf16x2_of(v0 - hf.x, v1 - hf.y);
        smu[OFF_BH + n * BPITCH + j] = h;
        smu[OFF_BL + n * BPITCH + j] = l;
    }
    if (tid < 32) ((float*)smu)[OFF_BI + tid] = bias[tid];

    // ---- input strip (230 pixels) -> bf16x2 hi/lo pairs ----
    const float2* inb2 = reinterpret_cast<const float2*>(in + (size_t)b * NPIX * 32);
    for (int i = tid; i < 230 * 16; i += 128) {
        int pix = i >> 4, j = i & 15;
        int gp = p0 + pix;
        float2 v = make_float2(0.f, 0.f);
        if (gp < NPIX) v = inb2[(size_t)gp * 16 + j];
        uint32_t h = bf16x2_of(v.x, v.y);
        float2 hf = bf16x2_to_f2(h);
        uint32_t l = bf16x2_of(v.x - hf.x, v.y - hf.y);
        smu[OFF_AH + pix * APITCH + j] = h;
        smu[OFF_AL + pix * APITCH + j] = l;
    }
    __syncthreads();

    int lane = tid & 31, wid = tid >> 5;
    int g = lane >> 2, tg = lane & 3;
    int m_warp = wid * 32;

    int  r0[2], r1[2];
    bool w0[2], w1[2];
#pragma unroll
    for (int mt = 0; mt < 2; mt++) {
        r0[mt] = m_warp + mt * 16 + g;
        r1[mt] = r0[mt] + 8;
        w0[mt] = (((p0 + r0[mt]) % GWW) == (GWW - 1));
        w1[mt] = (((p0 + r1[mt]) % GWW) == (GWW - 1));
    }

    float acc[2][4][4];
#pragma unroll
    for (int mt = 0; mt < 2; mt++)
#pragma unroll
        for (int nt = 0; nt < 4; nt++)
#pragma unroll
            for (int q = 0; q < 4; q++) acc[mt][nt][q] = 0.f;

#pragma unroll
    for (int s = 0; s < 8; s++) {                     // K = 128 = 8 x k16
        int tap = s >> 1, sh = s & 1;
        int toff = (tap >> 1) * GWW + (tap & 1);
        int dx = tap & 1;
        int cb = sh * 8 + tg;

        uint32_t AH[2][4], AL[2][4];
#pragma unroll
        for (int mt = 0; mt < 2; mt++) {
            bool z0 = dx && w0[mt], z1 = dx && w1[mt];
            int i0 = (r0[mt] + toff) * APITCH + cb;
            int i1 = (r1[mt] + toff) * APITCH + cb;
            AH[mt][0] = z0 ? 0u : smu[OFF_AH + i0];
            AH[mt][1] = z1 ? 0u : smu[OFF_AH + i1];
            AH[mt][2] = z0 ? 0u : smu[OFF_AH + i0 + 4];
            AH[mt][3] = z1 ? 0u : smu[OFF_AH + i1 + 4];
            AL[mt][0] = z0 ? 0u : smu[OFF_AL + i0];
            AL[mt][1] = z1 ? 0u : smu[OFF_AL + i1];
            AL[mt][2] = z0 ? 0u : smu[OFF_AL + i0 + 4];
            AL[mt][3] = z1 ? 0u : smu[OFF_AL + i1 + 4];
        }

        int kb = tap * 16 + sh * 8 + tg;
#pragma unroll
        for (int nt = 0; nt < 4; nt++) {
            int bo = (nt * 8 + g) * BPITCH + kb;
            uint32_t BH0 = smu[OFF_BH + bo];
            uint32_t BH1 = smu[OFF_BH + bo + 4];
            uint32_t BL0 = smu[OFF_BL + bo];
            uint32_t BL1 = smu[OFF_BL + bo + 4];
#pragma unroll
            for (int mt = 0; mt < 2; mt++) {
                MMA_BF16(acc[mt][nt], AH[mt], BH0, BH1);
                MMA_BF16(acc[mt][nt], AL[mt], BH0, BH1);
                MMA_BF16(acc[mt][nt], AH[mt], BL0, BL1);
            }
        }
    }

    // ---- epilogue: bias + relu, float2 stores ----
    const float* sbias = ((const float*)smu) + OFF_BI;
#pragma unroll
    for (int mt = 0; mt < 2; mt++) {
#pragma unroll
        for (int half = 0; half < 2; half++) {
            int pp = p0 + (half ? r1[mt] : r0[mt]);
            if (pp < NPIX) {
                float* op = outp + ((size_t)b * NPIX + pp) * 32;
#pragma unroll
                for (int nt = 0; nt < 4; nt++) {
                    int col = nt * 8 + tg * 2;
                    float2 v;
                    v.x = fmaxf(acc[mt][nt][half * 2 + 0] + sbias[col],     0.f);
                    v.y = fmaxf(acc[mt][nt][half * 2 + 1] + sbias[col + 1], 0.f);
                    *reinterpret_cast<float2*>(op + col) = v;
                }
            }
        }
    }
}

// ---------------------------------------------------------------------------
// Fused GRU encoder + autoregressive decoder. One block (128 thr) per batch row.
// Context grid read from g_bufB (conv3 output).
// ---------------------------------------------------------------------------
__device__ __forceinline__ float sigmoidf_(float v) { return 1.f / (1.f + expf(-v)); }
__device__ __forceinline__ float softplusf_(float v) {
    return fmaxf(v, 0.f) + log1pf(expf(-fabsf(v)));
}

__global__ void seq_kernel(const float* __restrict__ z,
                           const float* __restrict__ past,
                           const float* __restrict__ ewih, const float* __restrict__ ewhh,
                           const float* __restrict__ ebih, const float* __restrict__ ebhh,
                           const float* __restrict__ dwih, const float* __restrict__ dwhh,
                           const float* __restrict__ dbih, const float* __restrict__ dbhh,
                           const float* __restrict__ w1, const float* __restrict__ b1,
                           const float* __restrict__ w2, const float* __restrict__ b2,
                           float* __restrict__ out) {
    int b = blockIdx.x, tid = threadIdx.x;
    __shared__ __align__(16) float h[32];
    __shared__ float xv[34];
    __shared__ float sgi[96], sgh[96];
    __shared__ float hid[512];
    __shared__ float sls[4];
    __shared__ float y1s[2], y2s[2];

    if (tid < 32) h[tid] = 0.f;
    __syncthreads();

    for (int t = 0; t < TPAST; t++) {
        if (tid < 96) {
            float x0 = past[(b * TPAST + t) * 2];
            float x1 = past[(b * TPAST + t) * 2 + 1];
            float gi = ebih[tid] + x0 * ewih[tid * 2] + x1 * ewih[tid * 2 + 1];
            float gh = ebhh[tid];
            const float* wrp = ewhh + tid * 32;
#pragma unroll 8
            for (int k = 0; k < 32; k++) gh += h[k] * wrp[k];
            sgi[tid] = gi; sgh[tid] = gh;
        }
        __syncthreads();
        if (tid < 32) {
            float rr = sigmoidf_(sgi[tid] + sgh[tid]);
            float zg = sigmoidf_(sgi[32 + tid] + sgh[32 + tid]);
            float n  = tanhf(sgi[64 + tid] + rr * sgh[64 + tid]);
            h[tid] = (1.f - zg) * n + zg * h[tid];
        }
        __syncthreads();
    }

    if (tid == 0) {
        y2s[0] = past[(b * TPAST + 18) * 2]; y2s[1] = past[(b * TPAST + 18) * 2 + 1];
        y1s[0] = past[(b * TPAST + 19) * 2]; y1s[1] = past[(b * TPAST + 19) * 2 + 1];
    }

    float prod0 = 1.f, prod1 = 1.f;
    const float* ctx = g_bufB;

    for (int t = 0; t < TFUT; t++) {
        __syncthreads();
        if (tid < 32) {
            float q0 = y1s[0], q1 = y1s[1];
            float fyf = fminf(fmaxf(floorf(q0), 0.f), (float)(GHH - 2));
            float fxf = fminf(fmaxf(floorf(q1), 0.f), (float)(GWW - 2));
            float ay = fminf(fmaxf(q0 - fyf, 0.f), 1.f);
            float ax = fminf(fmaxf(q1 - fxf, 0.f), 1.f);
            int fy = (int)fyf, fx = (int)fxf;
            const float* gb = ctx + (((size_t)b * GHH + fy) * GWW + fx) * 32 + tid;
            float tl = gb[0], tr = gb[32], bl = gb[GWW * 32], br = gb[GWW * 32 + 32];
            float top = tl + ax * (tr - tl);
            float bot = bl + ax * (br - bl);
            xv[2 + tid] = top + ay * (bot - top);
            if (tid == 0) { xv[0] = q0; xv[1] = q1; }
        }
        __syncthreads();
        if (tid < 96) {
            float gi = dbih[tid];
            const float* wi = dwih + tid * 34;
#pragma unroll 2
            for (int k = 0; k < 34; k++) gi += xv[k] * wi[k];
            float gh = dbhh[tid];
            const float* wh = dwhh + tid * 32;
#pragma unroll 8
            for (int k = 0; k < 32; k++) gh += h[k] * wh[k];
            sgi[tid] = gi; sgh[tid] = gh;
        }
        __syncthreads();
        if (tid < 32) {
            float rr = sigmoidf_(sgi[tid] + sgh[tid]);
            float zg = sigmoidf_(sgi[32 + tid] + sgh[32 + tid]);
            float n  = tanhf(sgi[64 + tid] + rr * sgh[64 + tid]);
            h[tid] = (1.f - zg) * n + zg * h[tid];
        }
        __syncthreads();
#pragma unroll
        for (int j = 0; j < 4; j++) {
            int o = tid + 128 * j;
            float s = b1[o];
            const float4* wrp = reinterpret_cast<const float4*>(w1 + o * 32);
            const float4* hv = reinterpret_cast<const float4*>(h);
#pragma unroll
            for (int q = 0; q < 8; q++) {
                float4 wv = wrp[q]; float4 hh = hv[q];
                s += wv.x * hh.x + wv.y * hh.y + wv.z * hh.z + wv.w * hh.w;
            }
            hid[o] = s;
        }
        __syncthreads();
        {
            int ww = tid >> 5, lane = tid & 31;
            float pq = 0.f;
            const float* wrp = w2 + ww * 512;
#pragma unroll
            for (int i = 0; i < 16; i++) {
                int k = lane + 32 * i;
                pq += hid[k] * wrp[k];
            }
#pragma unroll
            for (int off = 16; off; off >>= 1) pq += __shfl_xor_sync(0xffffffffu, pq, off);
            if (lane == 0) sls[ww] = pq + b2[ww];
        }
        __syncthreads();
        if (tid == 0) {
            float loc0 = sls[0], loc1 = sls[1];
            float s0 = softplusf_(sls[2]);
            float s1 = softplusf_(sls[3]);
            float zt0 = z[(b * TFUT + t) * 2], zt1 = z[(b * TFUT + t) * 2 + 1];
            float yn0 = 2.f * y1s[0] - y2s[0] + loc0 + s0 * zt0;
            float yn1 = 2.f * y1s[1] - y2s[1] + loc1 + s1 * zt1;
            out[(b * TFUT + t) * 2]     = yn0;
            out[(b * TFUT + t) * 2 + 1] = yn1;
            prod0 *= s0; prod1 *= s1;
            y2s[0] = y1s[0]; y2s[1] = y1s[1];
            y1s[0] = yn0;    y1s[1] = yn1;
        }
    }
    if (tid == 0)
        out[BATCH * TFUT * 2 + b] = logf(fabsf(prod0)) + logf(fabsf(prod1));
}

// ---------------------------------------------------------------------------
extern "C" void kernel_launch(void* const* d_in, const int* in_sizes, int n_in,
                              void* d_out, int out_size) {
    const float* z    = (const float*)d_in[0];
    const float* past = (const float*)d_in[1];
    const float* lidar= (const float*)d_in[2];
    const float* c0w  = (const float*)d_in[3];
    const float* c0b  = (const float*)d_in[4];
    const float* c1w  = (const float*)d_in[5];
    const float* c1b  = (const float*)d_in[6];
    const float* c2w  = (const float*)d_in[7];
    const float* c2b  = (const float*)d_in[8];
    const float* c3w  = (const float*)d_in[9];
    const float* c3b  = (const float*)d_in[10];
    const float* ewih = (const float*)d_in[11];
    const float* ewhh = (const float*)d_in[12];
    const float* ebih = (const float*)d_in[13];
    const float* ebhh = (const float*)d_in[14];
    const float* dwih = (const float*)d_in[15];
    const float* dwhh = (const float*)d_in[16];
    const float* dbih = (const float*)d_in[17];
    const float* dbhh = (const float*)d_in[18];
    const float* w1   = (const float*)d_in[19];
    const float* b1   = (const float*)d_in[20];
    const float* w2   = (const float*)d_in[21];
    const float* b2   = (const float*)d_in[22];
    float* out = (float*)d_out;

    cudaFuncSetAttribute(convM_kernel, cudaFuncAttributeMaxDynamicSharedMemorySize,
                         CM_SMEM);

    conv0_kernel<<<(BATCH * NPIX + 255) / 256, 256>>>(lidar, c0w, c0b);

    dim3 cg((NPIX + 127) / 128, BATCH);
    convM_kernel<<<cg, 128, CM_SMEM>>>(c1w, c1b, 1); // A -> B
    convM_kernel<<<cg, 128, CM_SMEM>>>(c2w, c2b, 0); // B -> A
    convM_kernel<<<cg, 128, CM_SMEM>>>(c3w, c3b, 1); // A -> B

    seq_kernel<<<BATCH, 128>>>(z, past, ewih, ewhh, ebih, ebhh,
                               dwih, dwhh, dbih, dbhh, w1, b1, w2, b2, out);
}

// round 9
// speedup vs baseline: 1.8780x; 1.2331x over previous
#include <cuda_runtime.h>
#include <math.h>
#include <stdint.h>

#define BATCH 256
#define GHH 100
#define GWW 100
#define CH 32
#define TPAST 20
#define TFUT 30
#define NPIX (GHH * GWW)

// Ping-pong scratch for the conv stack (sanctioned __device__ global scratch).
__device__ __align__(128) float g_bufA[(size_t)BATCH*NPIX*CH];
__device__ __align__(128) float g_bufB[(size_t)BATCH*NPIX*CH];

// ---------------------------------------------------------------------------
// convF: 2x2 conv (32ch->32ch) as warp-level mma.sync bf16 m16n8k16 GEMM with
// 3-term compensation (D = Ah*Bh + Al*Bh + Ah*Bl).
//  - CTA = 224 threads (7 warps), 224-pixel strip; warp = 32 pixels x 32 ch.
//  - fuse=1: layer-1 mode, loader computes conv0(lidar)+relu on the fly
//    (eliminates the conv0 kernel and its 650MB HBM round trip).
//  - Strip row ZROW is an always-zero row; x-wrap handling is folded into
//    per-(row,tap) indices BEFORE the K loop -> inner loop has no selects.
// ---------------------------------------------------------------------------
#define PIXB 224
#define NTHR 224
#define APITCH 20                 // uint32 words per pixel (16 pairs + pad)
#define BPITCH 68                 // uint32 words per out-channel (64 pairs + pad)
#define NSTRIP 326                // data rows 0..324, ZROW = 325
#define ZROW 325
#define OFF_AH 0
#define OFF_AL (NSTRIP * APITCH)
#define OFF_BH (2 * NSTRIP * APITCH)
#define OFF_BL (OFF_BH + 32 * BPITCH)
#define OFF_BI (OFF_BL + 32 * BPITCH)
#define CM_WORDS (OFF_BI + 32)
#define CM_SMEM (CM_WORDS * 4)

#define MMA_BF16(C, A, B0, B1)                                               \
    asm volatile("mma.sync.aligned.m16n8k16.row.col.f32.bf16.bf16.f32 "      \
                 "{%0,%1,%2,%3}, {%4,%5,%6,%7}, {%8,%9}, {%0,%1,%2,%3};"     \
                 : "+f"(C[0]), "+f"(C[1]), "+f"(C[2]), "+f"(C[3])            \
                 : "r"(A[0]), "r"(A[1]), "r"(A[2]), "r"(A[3]),               \
                   "r"(B0), "r"(B1))

// pack (lo arg -> bits[15:0], hi arg -> bits[31:16])
__device__ __forceinline__ uint32_t bf16x2_of(float lo, float hi) {
    uint32_t r;
    asm("cvt.rn.bf16x2.f32 %0, %1, %2;" : "=r"(r) : "f"(hi), "f"(lo));
    return r;
}
__device__ __forceinline__ float2 bf16x2_to_f2(uint32_t u) {
    float2 r;
    r.x = __uint_as_float(u << 16);
    r.y = __uint_as_float(u & 0xFFFF0000u);
    return r;
}

__global__ void __launch_bounds__(NTHR) convF_kernel(
    const float* __restrict__ w,  const float* __restrict__ bias,
    const float* __restrict__ w0, const float* __restrict__ b0,
    const float* __restrict__ lidar, int srcIsA, int fuse) {
    extern __shared__ uint32_t smu[];
    const float* in   = srcIsA ? g_bufA : g_bufB;
    float*       outp = srcIsA ? g_bufB : g_bufA;

    int tid = threadIdx.x;
    int b   = blockIdx.y;
    int p0  = blockIdx.x * PIXB;

    // ---- weights -> bf16x2 hi/lo pairs: sB[oc][kpair] ----
    for (int i = tid; i < 2048; i += NTHR) {
        int n = i & 31, j = i >> 5;                  // j = k-pair 0..63
        float v0 = w[(2 * j) * 32 + n];
        float v1 = w[(2 * j + 1) * 32 + n];
        uint32_t h = bf16x2_of(v0, v1);
        float2 hf = bf16x2_to_f2(h);
        uint32_t l = bf16x2_of(v0 - hf.x, v1 - hf.y);
        smu[OFF_BH + n * BPITCH + j] = h;
        smu[OFF_BL + n * BPITCH + j] = l;
    }
    if (tid < 32) ((float*)smu)[OFF_BI + tid] = bias[tid];

    if (fuse) {
        // ---- layer-1 loader: conv0(lidar)+relu computed on the fly ----
        // Each thread owns a fixed 4-out-channel slice (sub = tid & 7).
        int sub = tid & 7;
        float wc[8][4], bc[4];
#pragma unroll
        for (int q = 0; q < 4; q++) bc[q] = b0[sub * 4 + q];
#pragma unroll
        for (int k = 0; k < 8; k++)
#pragma unroll
            for (int q = 0; q < 4; q++) wc[k][q] = w0[k * 32 + sub * 4 + q];

        const float* lb = lidar + (size_t)b * NPIX * 2;
        for (int u = tid; u < NSTRIP * 8; u += NTHR) {
            int pix = u >> 3;                       // sub == tid & 7 (NTHR % 8 == 0)
            int gp = p0 + pix;
            uint32_t h0 = 0, h1 = 0, l0 = 0, l1 = 0;
            if (pix < ZROW && gp < NPIX) {
                int y = gp / GWW, x = gp % GWW;
                bool xe = (x == GWW - 1), ye = (y == GHH - 1);
                float a[8];
#pragma unroll
                for (int dy = 0; dy < 2; dy++)
#pragma unroll
                    for (int dx = 0; dx < 2; dx++) {
                        bool ok = !(dy && ye) && !(dx && xe);
                        const float* ip = lb + ((size_t)(y + dy) * GWW + (x + dx)) * 2;
                        a[(dy * 2 + dx) * 2 + 0] = ok ? ip[0] : 0.f;
                        a[(dy * 2 + dx) * 2 + 1] = ok ? ip[1] : 0.f;
                    }
                float v[4];
#pragma unroll
                for (int q = 0; q < 4; q++) {
                    float s = bc[q];
#pragma unroll
                    for (int k = 0; k < 8; k++) s += a[k] * wc[k][q];
                    v[q] = fmaxf(s, 0.f);
                }
                h0 = bf16x2_of(v[0], v[1]);
                h1 = bf16x2_of(v[2], v[3]);
                float2 f0 = bf16x2_to_f2(h0), f1 = bf16x2_to_f2(h1);
                l0 = bf16x2_of(v[0] - f0.x, v[1] - f0.y);
                l1 = bf16x2_of(v[2] - f1.x, v[3] - f1.y);
            }
            int j = sub * 2;
            smu[OFF_AH + pix * APITCH + j]     = h0;
            smu[OFF_AH + pix * APITCH + j + 1] = h1;
            smu[OFF_AL + pix * APITCH + j]     = l0;
            smu[OFF_AL + pix * APITCH + j + 1] = l1;
        }
    } else {
        // ---- layers 2/3 loader: fp32 gmem -> bf16x2 hi/lo pairs ----
        const float2* inb2 = reinterpret_cast<const float2*>(in + (size_t)b * NPIX * 32);
        for (int i = tid; i < NSTRIP * 16; i += NTHR) {
            int pix = i >> 4, j = i & 15;
            int gp = p0 + pix;
            float2 v = make_float2(0.f, 0.f);
            if (pix < ZROW && gp < NPIX) v = inb2[(size_t)gp * 16 + j];
            uint32_t h = bf16x2_of(v.x, v.y);
            float2 hf = bf16x2_to_f2(h);
            uint32_t l = bf16x2_of(v.x - hf.x, v.y - hf.y);
            smu[OFF_AH + pix * APITCH + j] = h;
            smu[OFF_AL + pix * APITCH + j] = l;
        }
    }
    __syncthreads();

    int lane = tid & 31, wid = tid >> 5;            // wid 0..6
    int g = lane >> 2, tg = lane & 3;
    int m_warp = wid * 32;

    // Per-(row,tap) strip row indices with x-wrap folded to the zero row.
    int rows[2][2][4];
#pragma unroll
    for (int mt = 0; mt < 2; mt++)
#pragma unroll
        for (int half = 0; half < 2; half++) {
            int r = m_warp + mt * 16 + half * 8 + g;
            bool wrap = (((p0 + r) % GWW) == (GWW - 1));
#pragma unroll
            for (int tap = 0; tap < 4; tap++) {
                int rr = r + (tap >> 1) * GWW + (tap & 1);
                rows[mt][half][tap] = ((tap & 1) && wrap) ? ZROW : rr;
            }
        }

    float acc[2][4][4];
#pragma unroll
    for (int mt = 0; mt < 2; mt++)
#pragma unroll
        for (int nt = 0; nt < 4; nt++)
#pragma unroll
            for (int q = 0; q < 4; q++) acc[mt][nt][q] = 0.f;

#pragma unroll
    for (int s = 0; s < 8; s++) {                   // K = 128 = 8 x k16
        int tap = s >> 1, sh = s & 1;
        int cb = sh * 8 + tg;
        int kb = tap * 16 + sh * 8 + tg;

        uint32_t AH[2][4], AL[2][4];
#pragma unroll
        for (int mt = 0; mt < 2; mt++) {
            int i0 = rows[mt][0][tap] * APITCH + cb;
            int i1 = rows[mt][1][tap] * APITCH + cb;
            AH[mt][0] = smu[OFF_AH + i0];
            AH[mt][1] = smu[OFF_AH + i1];
            AH[mt][2] = smu[OFF_AH + i0 + 4];
            AH[mt][3] = smu[OFF_AH + i1 + 4];
            AL[mt][0] = smu[OFF_AL + i0];
            AL[mt][1] = smu[OFF_AL + i1];
            AL[mt][2] = smu[OFF_AL + i0 + 4];
            AL[mt][3] = smu[OFF_AL + i1 + 4];
        }

#pragma unroll
        for (int nt = 0; nt < 4; nt++) {
            int bo = (nt * 8 + g) * BPITCH + kb;
            uint32_t BH0 = smu[OFF_BH + bo];
            uint32_t BH1 = smu[OFF_BH + bo + 4];
            uint32_t BL0 = smu[OFF_BL + bo];
            uint32_t BL1 = smu[OFF_BL + bo + 4];
#pragma unroll
            for (int mt = 0; mt < 2; mt++) {
                MMA_BF16(acc[mt][nt], AH[mt], BH0, BH1);
                MMA_BF16(acc[mt][nt], AL[mt], BH0, BH1);
                MMA_BF16(acc[mt][nt], AH[mt], BL0, BL1);
            }
        }
    }

    // ---- epilogue: bias + relu, float2 stores ----
    const float* sbias = ((const float*)smu) + OFF_BI;
#pragma unroll
    for (int mt = 0; mt < 2; mt++) {
#pragma unroll
        for (int half = 0; half < 2; half++) {
            int pp = p0 + m_warp + mt * 16 + half * 8 + g;
            if (pp < NPIX) {
                float* op = outp + ((size_t)b * NPIX + pp) * 32;
#pragma unroll
                for (int nt = 0; nt < 4; nt++) {
                    int col = nt * 8 + tg * 2;
                    float2 v;
                    v.x = fmaxf(acc[mt][nt][half * 2 + 0] + sbias[col],     0.f);
                    v.y = fmaxf(acc[mt][nt][half * 2 + 1] + sbias[col + 1], 0.f);
                    *reinterpret_cast<float2*>(op + col) = v;
                }
            }
        }
    }
}

// ---------------------------------------------------------------------------
// Fused GRU encoder + autoregressive decoder. One block (128 thr) per batch row.
// Context grid read from g_bufB (conv3 output).
// ---------------------------------------------------------------------------
__device__ __forceinline__ float sigmoidf_(float v) { return 1.f / (1.f + expf(-v)); }
__device__ __forceinline__ float softplusf_(float v) {
    return fmaxf(v, 0.f) + log1pf(expf(-fabsf(v)));
}

__global__ void seq_kernel(const float* __restrict__ z,
                           const float* __restrict__ past,
                           const float* __restrict__ ewih, const float* __restrict__ ewhh,
                           const float* __restrict__ ebih, const float* __restrict__ ebhh,
                           const float* __restrict__ dwih, const float* __restrict__ dwhh,
                           const float* __restrict__ dbih, const float* __restrict__ dbhh,
                           const float* __restrict__ w1, const float* __restrict__ b1,
                           const float* __restrict__ w2, const float* __restrict__ b2,
                           float* __restrict__ out) {
    int b = blockIdx.x, tid = threadIdx.x;
    __shared__ __align__(16) float h[32];
    __shared__ float xv[34];
    __shared__ float sgi[96], sgh[96];
    __shared__ float hid[512];
    __shared__ float sls[4];
    __shared__ float y1s[2], y2s[2];

    if (tid < 32) h[tid] = 0.f;
    __syncthreads();

    for (int t = 0; t < TPAST; t++) {
        if (tid < 96) {
            float x0 = past[(b * TPAST + t) * 2];
            float x1 = past[(b * TPAST + t) * 2 + 1];
            float gi = ebih[tid] + x0 * ewih[tid * 2] + x1 * ewih[tid * 2 + 1];
            float gh = ebhh[tid];
            const float* wrp = ewhh + tid * 32;
#pragma unroll 8
            for (int k = 0; k < 32; k++) gh += h[k] * wrp[k];
            sgi[tid] = gi; sgh[tid] = gh;
        }
        __syncthreads();
        if (tid < 32) {
            float rr = sigmoidf_(sgi[tid] + sgh[tid]);
            float zg = sigmoidf_(sgi[32 + tid] + sgh[32 + tid]);
            float n  = tanhf(sgi[64 + tid] + rr * sgh[64 + tid]);
            h[tid] = (1.f - zg) * n + zg * h[tid];
        }
        __syncthreads();
    }

    if (tid == 0) {
        y2s[0] = past[(b * TPAST + 18) * 2]; y2s[1] = past[(b * TPAST + 18) * 2 + 1];
        y1s[0] = past[(b * TPAST + 19) * 2]; y1s[1] = past[(b * TPAST + 19) * 2 + 1];
    }

    float prod0 = 1.f, prod1 = 1.f;
    const float* ctx = g_bufB;

    for (int t = 0; t < TFUT; t++) {
        __syncthreads();
        if (tid < 32) {
            float q0 = y1s[0], q1 = y1s[1];
            float fyf = fminf(fmaxf(floorf(q0), 0.f), (float)(GHH - 2));
            float fxf = fminf(fmaxf(floorf(q1), 0.f), (float)(GWW - 2));
            float ay = fminf(fmaxf(q0 - fyf, 0.f), 1.f);
            float ax = fminf(fmaxf(q1 - fxf, 0.f), 1.f);
            int fy = (int)fyf, fx = (int)fxf;
            const float* gb = ctx + (((size_t)b * GHH + fy) * GWW + fx) * 32 + tid;
            float tl = gb[0], tr = gb[32], bl = gb[GWW * 32], br = gb[GWW * 32 + 32];
            float top = tl + ax * (tr - tl);
            float bot = bl + ax * (br - bl);
            xv[2 + tid] = top + ay * (bot - top);
            if (tid == 0) { xv[0] = q0; xv[1] = q1; }
        }
        __syncthreads();
        if (tid < 96) {
            float gi = dbih[tid];
            const float* wi = dwih + tid * 34;
#pragma unroll 2
            for (int k = 0; k < 34; k++) gi += xv[k] * wi[k];
            float gh = dbhh[tid];
            const float* wh = dwhh + tid * 32;
#pragma unroll 8
            for (int k = 0; k < 32; k++) gh += h[k] * wh[k];
            sgi[tid] = gi; sgh[tid] = gh;
        }
        __syncthreads();
        if (tid < 32) {
            float rr = sigmoidf_(sgi[tid] + sgh[tid]);
            float zg = sigmoidf_(sgi[32 + tid] + sgh[32 + tid]);
            float n  = tanhf(sgi[64 + tid] + rr * sgh[64 + tid]);
            h[tid] = (1.f - zg) * n + zg * h[tid];
        }
        __syncthreads();
#pragma unroll
        for (int j = 0; j < 4; j++) {
            int o = tid + 128 * j;
            float s = b1[o];
            const float4* wrp = reinterpret_cast<const float4*>(w1 + o * 32);
            const float4* hv = reinterpret_cast<const float4*>(h);
#pragma unroll
            for (int q = 0; q < 8; q++) {
                float4 wv = wrp[q]; float4 hh = hv[q];
                s += wv.x * hh.x + wv.y * hh.y + wv.z * hh.z + wv.w * hh.w;
            }
            hid[o] = s;
        }
        __syncthreads();
        {
            int ww = tid >> 5, lane = tid & 31;
            float pq = 0.f;
            const float* wrp = w2 + ww * 512;
#pragma unroll
            for (int i = 0; i < 16; i++) {
                int k = lane + 32 * i;
                pq += hid[k] * wrp[k];
            }
#pragma unroll
            for (int off = 16; off; off >>= 1) pq += __shfl_xor_sync(0xffffffffu, pq, off);
            if (lane == 0) sls[ww] = pq + b2[ww];
        }
        __syncthreads();
        if (tid == 0) {
            float loc0 = sls[0], loc1 = sls[1];
            float s0 = softplusf_(sls[2]);
            float s1 = softplusf_(sls[3]);
            float zt0 = z[(b * TFUT + t) * 2], zt1 = z[(b * TFUT + t) * 2 + 1];
            float yn0 = 2.f * y1s[0] - y2s[0] + loc0 + s0 * zt0;
            float yn1 = 2.f * y1s[1] - y2s[1] + loc1 + s1 * zt1;
            out[(b * TFUT + t) * 2]     = yn0;
            out[(b * TFUT + t) * 2 + 1] = yn1;
            prod0 *= s0; prod1 *= s1;
            y2s[0] = y1s[0]; y2s[1] = y1s[1];
            y1s[0] = yn0;    y1s[1] = yn1;
        }
    }
    if (tid == 0)
        out[BATCH * TFUT * 2 + b] = logf(fabsf(prod0)) + logf(fabsf(prod1));
}

// ---------------------------------------------------------------------------
extern "C" void kernel_launch(void* const* d_in, const int* in_sizes, int n_in,
                              void* d_out, int out_size) {
    const float* z    = (const float*)d_in[0];
    const float* past = (const float*)d_in[1];
    const float* lidar= (const float*)d_in[2];
    const float* c0w  = (const float*)d_in[3];
    const float* c0b  = (const float*)d_in[4];
    const float* c1w  = (const float*)d_in[5];
    const float* c1b  = (const float*)d_in[6];
    const float* c2w  = (const float*)d_in[7];
    const float* c2b  = (const float*)d_in[8];
    const float* c3w  = (const float*)d_in[9];
    const float* c3b  = (const float*)d_in[10];
    const float* ewih = (const float*)d_in[11];
    const float* ewhh = (const float*)d_in[12];
    const float* ebih = (const float*)d_in[13];
    const float* ebhh = (const float*)d_in[14];
    const float* dwih = (const float*)d_in[15];
    const float* dwhh = (const float*)d_in[16];
    const float* dbih = (const float*)d_in[17];
    const float* dbhh = (const float*)d_in[18];
    const float* w1   = (const float*)d_in[19];
    const float* b1   = (const float*)d_in[20];
    const float* w2   = (const float*)d_in[21];
    const float* b2   = (const float*)d_in[22];
    float* out = (float*)d_out;

    cudaFuncSetAttribute(convF_kernel, cudaFuncAttributeMaxDynamicSharedMemorySize,
                         CM_SMEM);

    dim3 cg((NPIX + PIXB - 1) / PIXB, BATCH);
    // layer 1 (conv0 fused into the loader): lidar -> g_bufB
    convF_kernel<<<cg, NTHR, CM_SMEM>>>(c1w, c1b, c0w, c0b, lidar, 1, 1);
    // layer 2: g_bufB -> g_bufA
    convF_kernel<<<cg, NTHR, CM_SMEM>>>(c2w, c2b, c0w, c0b, lidar, 0, 0);
    // layer 3: g_bufA -> g_bufB
    convF_kernel<<<cg, NTHR, CM_SMEM>>>(c3w, c3b, c0w, c0b, lidar, 1, 0);

    seq_kernel<<<BATCH, 128>>>(z, past, ewih, ewhh, ebih, ebhh,
                               dwih, dwhh, dbih, dbhh, w1, b1, w2, b2, out);
}

// round 10
// speedup vs baseline: 2.3105x; 1.2303x over previous
#include <cuda_runtime.h>
#include <math.h>
#include <stdint.h>

#define BATCH 256
#define GHH 100
#define GWW 100
#define CH 32
#define TPAST 20
#define TFUT 30
#define NPIX (GHH * GWW)

// Ping-pong scratch for the conv stack (sanctioned __device__ global scratch).
__device__ __align__(128) float g_bufA[(size_t)BATCH*NPIX*CH];
__device__ __align__(128) float g_bufB[(size_t)BATCH*NPIX*CH];
// Collapsed MLP: W = mlp_w2 @ mlp_w1 (4x32), wb = mlp_w2 @ mlp_b1 + mlp_b2.
__device__ float g_W[128];
__device__ float g_wb[4];

// ---------------------------------------------------------------------------
// convF: 2x2 conv (32ch->32ch) as warp-level mma.sync bf16 m16n8k16 GEMM with
// 3-term compensation (D = Ah*Bh + Al*Bh + Ah*Bl).  (unchanged from R9)
// ---------------------------------------------------------------------------
#define PIXB 224
#define NTHR 224
#define APITCH 20
#define BPITCH 68
#define NSTRIP 326
#define ZROW 325
#define OFF_AH 0
#define OFF_AL (NSTRIP * APITCH)
#define OFF_BH (2 * NSTRIP * APITCH)
#define OFF_BL (OFF_BH + 32 * BPITCH)
#define OFF_BI (OFF_BL + 32 * BPITCH)
#define CM_WORDS (OFF_BI + 32)
#define CM_SMEM (CM_WORDS * 4)

#define MMA_BF16(C, A, B0, B1)                                               \
    asm volatile("mma.sync.aligned.m16n8k16.row.col.f32.bf16.bf16.f32 "      \
                 "{%0,%1,%2,%3}, {%4,%5,%6,%7}, {%8,%9}, {%0,%1,%2,%3};"     \
                 : "+f"(C[0]), "+f"(C[1]), "+f"(C[2]), "+f"(C[3])            \
                 : "r"(A[0]), "r"(A[1]), "r"(A[2]), "r"(A[3]),               \
                   "r"(B0), "r"(B1))

__device__ __forceinline__ uint32_t bf16x2_of(float lo, float hi) {
    uint32_t r;
    asm("cvt.rn.bf16x2.f32 %0, %1, %2;" : "=r"(r) : "f"(hi), "f"(lo));
    return r;
}
__device__ __forceinline__ float2 bf16x2_to_f2(uint32_t u) {
    float2 r;
    r.x = __uint_as_float(u << 16);
    r.y = __uint_as_float(u & 0xFFFF0000u);
    return r;
}

__global__ void __launch_bounds__(NTHR) convF_kernel(
    const float* __restrict__ w,  const float* __restrict__ bias,
    const float* __restrict__ w0, const float* __restrict__ b0,
    const float* __restrict__ lidar, int srcIsA, int fuse) {
    extern __shared__ uint32_t smu[];
    const float* in   = srcIsA ? g_bufA : g_bufB;
    float*       outp = srcIsA ? g_bufB : g_bufA;

    int tid = threadIdx.x;
    int b   = blockIdx.y;
    int p0  = blockIdx.x * PIXB;

    for (int i = tid; i < 2048; i += NTHR) {
        int n = i & 31, j = i >> 5;
        float v0 = w[(2 * j) * 32 + n];
        float v1 = w[(2 * j + 1) * 32 + n];
        uint32_t h = bf16x2_of(v0, v1);
        float2 hf = bf16x2_to_f2(h);
        uint32_t l = bf16x2_of(v0 - hf.x, v1 - hf.y);
        smu[OFF_BH + n * BPITCH + j] = h;
        smu[OFF_BL + n * BPITCH + j] = l;
    }
    if (tid < 32) ((float*)smu)[OFF_BI + tid] = bias[tid];

    if (fuse) {
        int sub = tid & 7;
        float wc[8][4], bc[4];
#pragma unroll
        for (int q = 0; q < 4; q++) bc[q] = b0[sub * 4 + q];
#pragma unroll
        for (int k = 0; k < 8; k++)
#pragma unroll
            for (int q = 0; q < 4; q++) wc[k][q] = w0[k * 32 + sub * 4 + q];

        const float* lb = lidar + (size_t)b * NPIX * 2;
        for (int u = tid; u < NSTRIP * 8; u += NTHR) {
            int pix = u >> 3;
            int gp = p0 + pix;
            uint32_t h0 = 0, h1 = 0, l0 = 0, l1 = 0;
            if (pix < ZROW && gp < NPIX) {
                int y = gp / GWW, x = gp % GWW;
                bool xe = (x == GWW - 1), ye = (y == GHH - 1);
                float a[8];
#pragma unroll
                for (int dy = 0; dy < 2; dy++)
#pragma unroll
                    for (int dx = 0; dx < 2; dx++) {
                        bool ok = !(dy && ye) && !(dx && xe);
                        const float* ip = lb + ((size_t)(y + dy) * GWW + (x + dx)) * 2;
                        a[(dy * 2 + dx) * 2 + 0] = ok ? ip[0] : 0.f;
                        a[(dy * 2 + dx) * 2 + 1] = ok ? ip[1] : 0.f;
                    }
                float v[4];
#pragma unroll
                for (int q = 0; q < 4; q++) {
                    float s = bc[q];
#pragma unroll
                    for (int k = 0; k < 8; k++) s += a[k] * wc[k][q];
                    v[q] = fmaxf(s, 0.f);
                }
                h0 = bf16x2_of(v[0], v[1]);
                h1 = bf16x2_of(v[2], v[3]);
                float2 f0 = bf16x2_to_f2(h0), f1 = bf16x2_to_f2(h1);
                l0 = bf16x2_of(v[0] - f0.x, v[1] - f0.y);
                l1 = bf16x2_of(v[2] - f1.x, v[3] - f1.y);
            }
            int j = sub * 2;
            smu[OFF_AH + pix * APITCH + j]     = h0;
            smu[OFF_AH + pix * APITCH + j + 1] = h1;
            smu[OFF_AL + pix * APITCH + j]     = l0;
            smu[OFF_AL + pix * APITCH + j + 1] = l1;
        }
    } else {
        const float2* inb2 = reinterpret_cast<const float2*>(in + (size_t)b * NPIX * 32);
        for (int i = tid; i < NSTRIP * 16; i += NTHR) {
            int pix = i >> 4, j = i & 15;
            int gp = p0 + pix;
            float2 v = make_float2(0.f, 0.f);
            if (pix < ZROW && gp < NPIX) v = inb2[(size_t)gp * 16 + j];
            uint32_t h = bf16x2_of(v.x, v.y);
            float2 hf = bf16x2_to_f2(h);
            uint32_t l = bf16x2_of(v.x - hf.x, v.y - hf.y);
            smu[OFF_AH + pix * APITCH + j] = h;
            smu[OFF_AL + pix * APITCH + j] = l;
        }
    }
    __syncthreads();

    int lane = tid & 31, wid = tid >> 5;
    int g = lane >> 2, tg = lane & 3;
    int m_warp = wid * 32;

    int rows[2][2][4];
#pragma unroll
    for (int mt = 0; mt < 2; mt++)
#pragma unroll
        for (int half = 0; half < 2; half++) {
            int r = m_warp + mt * 16 + half * 8 + g;
            bool wrap = (((p0 + r) % GWW) == (GWW - 1));
#pragma unroll
            for (int tap = 0; tap < 4; tap++) {
                int rr = r + (tap >> 1) * GWW + (tap & 1);
                rows[mt][half][tap] = ((tap & 1) && wrap) ? ZROW : rr;
            }
        }

    float acc[2][4][4];
#pragma unroll
    for (int mt = 0; mt < 2; mt++)
#pragma unroll
        for (int nt = 0; nt < 4; nt++)
#pragma unroll
            for (int q = 0; q < 4; q++) acc[mt][nt][q] = 0.f;

#pragma unroll
    for (int s = 0; s < 8; s++) {
        int tap = s >> 1, sh = s & 1;
        int cb = sh * 8 + tg;
        int kb = tap * 16 + sh * 8 + tg;

        uint32_t AH[2][4], AL[2][4];
#pragma unroll
        for (int mt = 0; mt < 2; mt++) {
            int i0 = rows[mt][0][tap] * APITCH + cb;
            int i1 = rows[mt][1][tap] * APITCH + cb;
            AH[mt][0] = smu[OFF_AH + i0];
            AH[mt][1] = smu[OFF_AH + i1];
            AH[mt][2] = smu[OFF_AH + i0 + 4];
            AH[mt][3] = smu[OFF_AH + i1 + 4];
            AL[mt][0] = smu[OFF_AL + i0];
            AL[mt][1] = smu[OFF_AL + i1];
            AL[mt][2] = smu[OFF_AL + i0 + 4];
            AL[mt][3] = smu[OFF_AL + i1 + 4];
        }

#pragma unroll
        for (int nt = 0; nt < 4; nt++) {
            int bo = (nt * 8 + g) * BPITCH + kb;
            uint32_t BH0 = smu[OFF_BH + bo];
            uint32_t BH1 = smu[OFF_BH + bo + 4];
            uint32_t BL0 = smu[OFF_BL + bo];
            uint32_t BL1 = smu[OFF_BL + bo + 4];
#pragma unroll
            for (int mt = 0; mt < 2; mt++) {
                MMA_BF16(acc[mt][nt], AH[mt], BH0, BH1);
                MMA_BF16(acc[mt][nt], AL[mt], BH0, BH1);
                MMA_BF16(acc[mt][nt], AH[mt], BL0, BL1);
            }
        }
    }

    const float* sbias = ((const float*)smu) + OFF_BI;
#pragma unroll
    for (int mt = 0; mt < 2; mt++) {
#pragma unroll
        for (int half = 0; half < 2; half++) {
            int pp = p0 + m_warp + mt * 16 + half * 8 + g;
            if (pp < NPIX) {
                float* op = outp + ((size_t)b * NPIX + pp) * 32;
#pragma unroll
                for (int nt = 0; nt < 4; nt++) {
                    int col = nt * 8 + tg * 2;
                    float2 v;
                    v.x = fmaxf(acc[mt][nt][half * 2 + 0] + sbias[col],     0.f);
                    v.y = fmaxf(acc[mt][nt][half * 2 + 1] + sbias[col + 1], 0.f);
                    *reinterpret_cast<float2*>(op + col) = v;
                }
            }
        }
    }
}

// ---------------------------------------------------------------------------
// mlp_collapse: W(4x32) = w2(4x512) @ w1(512x32); wb = w2 @ b1 + b2.
// One block, 128 threads, coalesced loads.
// ---------------------------------------------------------------------------
__global__ void __launch_bounds__(128) mlp_collapse_kernel(
    const float* __restrict__ w1, const float* __restrict__ b1,
    const float* __restrict__ w2, const float* __restrict__ b2) {
    int tid = threadIdx.x;
    int o = tid >> 5, i = tid & 31;
    const float* w2r = w2 + o * 512;
    float s = 0.f;
#pragma unroll 8
    for (int k = 0; k < 512; k++) s += w2r[k] * w1[k * 32 + i];
    g_W[tid] = s;
    if (tid < 4) {
        const float* wr = w2 + tid * 512;
        float sb = 0.f;
#pragma unroll 8
        for (int k = 0; k < 512; k++) sb += wr[k] * b1[k];
        g_wb[tid] = sb + b2[tid];
    }
}

// ---------------------------------------------------------------------------
// seq: warp-per-batch-row GRU encoder + autoregressive decoder. 32 threads per
// block, zero __syncthreads in the recurrence; h in registers (lane i owns
// h_i, full vector mirrored in harr via shuffles). GRU weights staged in smem
// with stride-36 rows (16B-aligned and conflict-free float4 LDS).
// MLP collapsed to ls = g_W @ h + g_wb (butterfly-reduced).
// ---------------------------------------------------------------------------
#define FULLM 0xffffffffu
__device__ __forceinline__ float sigmoidf_(float v) { return 1.f / (1.f + expf(-v)); }
__device__ __forceinline__ float softplusf_(float v) {
    return fmaxf(v, 0.f) + log1pf(expf(-fabsf(v)));
}

__global__ void __launch_bounds__(32) seq_kernel(
    const float* __restrict__ z,    const float* __restrict__ past,
    const float* __restrict__ ewih, const float* __restrict__ ewhh,
    const float* __restrict__ ebih, const float* __restrict__ ebhh,
    const float* __restrict__ dwih, const float* __restrict__ dwhh,
    const float* __restrict__ dbih, const float* __restrict__ dbhh,
    float* __restrict__ out) {
    int b = blockIdx.x, i = threadIdx.x;

    __shared__ __align__(16) float s_ewhh[96 * 36];
    __shared__ __align__(16) float s_dwhh[96 * 36];
    __shared__ __align__(16) float s_dwih[96 * 36];   // [0,1]=y1 wts, [4..35]=interp wts
    __shared__ float s_eih[192];
    __shared__ float s_ebih[96], s_ebhh[96], s_dbih[96], s_dbhh[96];
    __shared__ float s_W[128], s_wb[4];

    for (int u = i; u < 3072; u += 32) {
        int r = u >> 5, c = u & 31;
        s_ewhh[r * 36 + c] = ewhh[u];
        s_dwhh[r * 36 + c] = dwhh[u];
    }
    for (int u = i; u < 96 * 34; u += 32) {
        int r = u / 34, c = u % 34;
        s_dwih[r * 36 + (c < 2 ? c : c + 2)] = dwih[u];
    }
    for (int u = i; u < 192; u += 32) s_eih[u] = ewih[u];
    for (int u = i; u < 96; u += 32) {
        s_ebih[u] = ebih[u]; s_ebhh[u] = ebhh[u];
        s_dbih[u] = dbih[u]; s_dbhh[u] = dbhh[u];
    }
    for (int u = i; u < 128; u += 32) s_W[u] = g_W[u];
    if (i < 4) s_wb[i] = g_wb[i];
    __syncwarp();

    float hi = 0.f;
    float harr[32];
#pragma unroll
    for (int k = 0; k < 32; k++) harr[k] = 0.f;

    // ---- encoder ----
    const float* pb = past + (size_t)b * TPAST * 2;
    for (int t = 0; t < TPAST; t++) {
        float x0 = pb[2 * t], x1 = pb[2 * t + 1];
        float g0 = s_ebih[i]      + x0 * s_eih[2 * i]            + x1 * s_eih[2 * i + 1];
        float g1 = s_ebih[32 + i] + x0 * s_eih[2 * (32 + i)]     + x1 * s_eih[2 * (32 + i) + 1];
        float g2 = s_ebih[64 + i] + x0 * s_eih[2 * (64 + i)]     + x1 * s_eih[2 * (64 + i) + 1];
        float h0 = s_ebhh[i], h1 = s_ebhh[32 + i], h2 = s_ebhh[64 + i];
        const float4* w0p = (const float4*)&s_ewhh[i * 36];
        const float4* w1p = (const float4*)&s_ewhh[(32 + i) * 36];
        const float4* w2p = (const float4*)&s_ewhh[(64 + i) * 36];
#pragma unroll
        for (int q = 0; q < 8; q++) {
            float4 a0 = w0p[q], a1 = w1p[q], a2 = w2p[q];
            float k0 = harr[4 * q], k1 = harr[4 * q + 1], k2 = harr[4 * q + 2], k3 = harr[4 * q + 3];
            h0 += k0 * a0.x + k1 * a0.y + k2 * a0.z + k3 * a0.w;
            h1 += k0 * a1.x + k1 * a1.y + k2 * a1.z + k3 * a1.w;
            h2 += k0 * a2.x + k1 * a2.y + k2 * a2.z + k3 * a2.w;
        }
        float rg = sigmoidf_(g0 + h0);
        float zg = sigmoidf_(g1 + h1);
        float nn = tanhf(g2 + rg * h2);
        hi = (1.f - zg) * nn + zg * hi;
#pragma unroll
        for (int k = 0; k < 32; k++) harr[k] = __shfl_sync(FULLM, hi, k);
    }

    float y1x = pb[2 * 19], y1y = pb[2 * 19 + 1];
    float y2x = pb[2 * 18], y2y = pb[2 * 18 + 1];
    float prod0 = 1.f, prod1 = 1.f;
    const float* ctx = g_bufB + (size_t)b * NPIX * 32;
    const float* zb = z + (size_t)b * TFUT * 2;

    // ---- decoder ----
    for (int t = 0; t < TFUT; t++) {
        // bilinear (lane i = channel i)
        float fyf = fminf(fmaxf(floorf(y1x), 0.f), (float)(GHH - 2));
        float fxf = fminf(fmaxf(floorf(y1y), 0.f), (float)(GWW - 2));
        float ay = fminf(fmaxf(y1x - fyf, 0.f), 1.f);
        float ax = fminf(fmaxf(y1y - fxf, 0.f), 1.f);
        int fy = (int)fyf, fx = (int)fxf;
        const float* gb = ctx + ((size_t)fy * GWW + fx) * 32 + i;
        float tl = gb[0], tr = gb[32], bl = gb[GWW * 32], br = gb[GWW * 32 + 32];
        float top = tl + ax * (tr - tl);
        float bot = bl + ax * (br - bl);
        float xi = top + ay * (bot - top);
        float xarr[32];
#pragma unroll
        for (int k = 0; k < 32; k++) xarr[k] = __shfl_sync(FULLM, xi, k);

        // gates
        float g0 = s_dbih[i]      + y1x * s_dwih[i * 36]            + y1y * s_dwih[i * 36 + 1];
        float g1 = s_dbih[32 + i] + y1x * s_dwih[(32 + i) * 36]     + y1y * s_dwih[(32 + i) * 36 + 1];
        float g2 = s_dbih[64 + i] + y1x * s_dwih[(64 + i) * 36]     + y1y * s_dwih[(64 + i) * 36 + 1];
        float h0 = s_dbhh[i], h1 = s_dbhh[32 + i], h2 = s_dbhh[64 + i];
        {
            const float4* xi0 = (const float4*)&s_dwih[i * 36 + 4];
            const float4* xi1 = (const float4*)&s_dwih[(32 + i) * 36 + 4];
            const float4* xi2 = (const float4*)&s_dwih[(64 + i) * 36 + 4];
            const float4* w0p = (const float4*)&s_dwhh[i * 36];
            const float4* w1p = (const float4*)&s_dwhh[(32 + i) * 36];
            const float4* w2p = (const float4*)&s_dwhh[(64 + i) * 36];
#pragma unroll
            for (int q = 0; q < 8; q++) {
                float4 a0 = xi0[q], a1 = xi1[q], a2 = xi2[q];
                float k0 = xarr[4 * q], k1 = xarr[4 * q + 1], k2 = xarr[4 * q + 2], k3 = xarr[4 * q + 3];
                g0 += k0 * a0.x + k1 * a0.y + k2 * a0.z + k3 * a0.w;
                g1 += k0 * a1.x + k1 * a1.y + k2 * a1.z + k3 * a1.w;
                g2 += k0 * a2.x + k1 * a2.y + k2 * a2.z + k3 * a2.w;
                float4 c0 = w0p[q], c1 = w1p[q], c2 = w2p[q];
                float m0 = harr[4 * q], m1 = harr[4 * q + 1], m2 = harr[4 * q + 2], m3 = harr[4 * q + 3];
                h0 += m0 * c0.x + m1 * c0.y + m2 * c0.z + m3 * c0.w;
                h1 += m0 * c1.x + m1 * c1.y + m2 * c1.z + m3 * c1.w;
                h2 += m0 * c2.x + m1 * c2.y + m2 * c2.z + m3 * c2.w;
            }
        }
        float rg = sigmoidf_(g0 + h0);
        float zg = sigmoidf_(g1 + h1);
        float nn = tanhf(g2 + rg * h2);
        hi = (1.f - zg) * nn + zg * hi;
#pragma unroll
        for (int k = 0; k < 32; k++) harr[k] = __shfl_sync(FULLM, hi, k);

        // ls = W @ h + wb (butterfly; all lanes end with full sums)
        float p0 = s_W[i] * hi;
        float p1 = s_W[32 + i] * hi;
        float p2 = s_W[64 + i] * hi;
        float p3 = s_W[96 + i] * hi;
#pragma unroll
        for (int off = 16; off; off >>= 1) {
            p0 += __shfl_xor_sync(FULLM, p0, off);
            p1 += __shfl_xor_sync(FULLM, p1, off);
            p2 += __shfl_xor_sync(FULLM, p2, off);
            p3 += __shfl_xor_sync(FULLM, p3, off);
        }
        float loc0 = p0 + s_wb[0], loc1 = p1 + s_wb[1];
        float s0 = softplusf_(p2 + s_wb[2]);
        float s1 = softplusf_(p3 + s_wb[3]);
        float zt0 = zb[2 * t], zt1 = zb[2 * t + 1];
        float ynx = 2.f * y1x - y2x + loc0 + s0 * zt0;
        float yny = 2.f * y1y - y2y + loc1 + s1 * zt1;
        if (i == 0) {
            out[((size_t)b * TFUT + t) * 2]     = ynx;
            out[((size_t)b * TFUT + t) * 2 + 1] = yny;
        }
        prod0 *= s0; prod1 *= s1;
        y2x = y1x; y2y = y1y;
        y1x = ynx; y1y = yny;
    }
    if (i == 0)
        out[(size_t)BATCH * TFUT * 2 + b] = logf(fabsf(prod0)) + logf(fabsf(prod1));
}

// ---------------------------------------------------------------------------
extern "C" void kernel_launch(void* const* d_in, const int* in_sizes, int n_in,
                              void* d_out, int out_size) {
    const float* z    = (const float*)d_in[0];
    const float* past = (const float*)d_in[1];
    const float* lidar= (const float*)d_in[2];
    const float* c0w  = (const float*)d_in[3];
    const float* c0b  = (const float*)d_in[4];
    const float* c1w  = (const float*)d_in[5];
    const float* c1b  = (const float*)d_in[6];
    const float* c2w  = (const float*)d_in[7];
    const float* c2b  = (const float*)d_in[8];
    const float* c3w  = (const float*)d_in[9];
    const float* c3b  = (const float*)d_in[10];
    const float* ewih = (const float*)d_in[11];
    const float* ewhh = (const float*)d_in[12];
    const float* ebih = (const float*)d_in[13];
    const float* ebhh = (const float*)d_in[14];
    const float* dwih = (const float*)d_in[15];
    const float* dwhh = (const float*)d_in[16];
    const float* dbih = (const float*)d_in[17];
    const float* dbhh = (const float*)d_in[18];
    const float* w1   = (const float*)d_in[19];
    const float* b1   = (const float*)d_in[20];
    const float* w2   = (const float*)d_in[21];
    const float* b2   = (const float*)d_in[22];
    float* out = (float*)d_out;

    cudaFuncSetAttribute(convF_kernel, cudaFuncAttributeMaxDynamicSharedMemorySize,
                         CM_SMEM);

    mlp_collapse_kernel<<<1, 128>>>(w1, b1, w2, b2);

    dim3 cg((NPIX + PIXB - 1) / PIXB, BATCH);
    convF_kernel<<<cg, NTHR, CM_SMEM>>>(c1w, c1b, c0w, c0b, lidar, 1, 1);
    convF_kernel<<<cg, NTHR, CM_SMEM>>>(c2w, c2b, c0w, c0b, lidar, 0, 0);
    convF_kernel<<<cg, NTHR, CM_SMEM>>>(c3w, c3b, c0w, c0b, lidar, 1, 0);

    seq_kernel<<<BATCH, 32>>>(z, past, ewih, ewhh, ebih, ebhh,
                              dwih, dwhh, dbih, dbhh, out);
}